// round 10
// baseline (speedup 1.0000x reference)
#include <cuda_runtime.h>
#include <cstdint>

// Problem dims
#define B_ 32
#define P_ 12
#define N_ 512
#define F_ 64
#define D_ 256
#define Q_ 12
#define DT_ 0.1f

static const int BQN = B_ * Q_ * N_;  // 196608
#define NBQ (B_ * Q_)                 // 384

// ---------------- scratch (device globals; no runtime alloc) ----------------
__device__ float g_tmp  [(size_t)B_ * Q_ * N_ * F_];     // mixed inputs (tf32 bits)
__device__ float g_h    [(size_t)B_ * Q_ * N_ * D_];     // hidden (tf32 bits)
__device__ float g_qkv  [(size_t)B_ * Q_ * N_ * 3 * D_]; // q|k|v, ld=768 (tf32 bits)
__device__ float g_S    [(size_t)B_ * Q_ * N_ * N_];     // exp'd scores (fp32)
__device__ float g_CP   [(size_t)12 * N_ * N_];          // c_k = (I+DT*A)^k - I, tf32
__device__ float g_WinT [(size_t)D_ * F_];               // W_in^T  tf32
__device__ float g_WqkvT[(size_t)3 * D_ * D_];           // Wqkv^T  tf32
__device__ float g_WoutT[(size_t)F_ * D_];               // W_out^T tf32
__device__ float g_fac  [(size_t)NBQ * N_];              // 1 / rowsum(exp scores)

// ---------------- helpers ----------------------------------------------------
__device__ __forceinline__ uint32_t f2tf32(float f) {
    uint32_t u;
    asm("cvt.rna.tf32.f32 %0, %1;" : "=r"(u) : "f"(f));
    return u;
}
__device__ __forceinline__ float roundtf(float f) { return __uint_as_float(f2tf32(f)); }

__device__ __forceinline__ void mma_tf32(float* c, const uint32_t* a, const uint32_t* b) {
    asm volatile(
        "mma.sync.aligned.m16n8k8.row.col.f32.tf32.tf32.f32 "
        "{%0,%1,%2,%3}, {%4,%5,%6,%7}, {%8,%9}, {%0,%1,%2,%3};"
        : "+f"(c[0]), "+f"(c[1]), "+f"(c[2]), "+f"(c[3])
        : "r"(a[0]), "r"(a[1]), "r"(a[2]), "r"(a[3]),
          "r"(b[0]), "r"(b[1]));
}

__device__ __forceinline__ void ldsm_x4(uint32_t* r, uint32_t addr) {
    asm volatile("ldmatrix.sync.aligned.m8n8.x4.shared.b16 {%0,%1,%2,%3}, [%4];"
                 : "=r"(r[0]), "=r"(r[1]), "=r"(r[2]), "=r"(r[3]) : "r"(addr));
}

__device__ __forceinline__ void cp_async16(uint32_t smem_dst, const void* gsrc) {
    asm volatile("cp.async.cg.shared.global [%0], [%1], 16;\n" :: "r"(smem_dst), "l"(gsrc));
}

// ---------------- K1: tmp = time-mix(inputs), tf32-rounded -------------------
__global__ __launch_bounds__(256) void mix_kernel(const float* __restrict__ in,
                                                  const float* __restrict__ T) {
    __shared__ float Ts[P_][Q_];
    int t = threadIdx.x;
    if (t < P_ * Q_) Ts[t / Q_][t % Q_] = T[t];
    __syncthreads();
    long idx = (long)blockIdx.x * blockDim.x + t;
    if (idx >= (long)B_ * N_ * F_) return;
    int f = (int)(idx % F_);
    int n = (int)((idx / F_) % N_);
    int b = (int)(idx / ((long)F_ * N_));
    float vals[P_];
    const float* ip = in + ((long)b * P_ * N_ + n) * F_ + f;
#pragma unroll
    for (int p = 0; p < P_; p++) vals[p] = ip[(long)p * N_ * F_];
    float* op = g_tmp + ((long)b * Q_ * N_ + n) * F_ + f;
#pragma unroll
    for (int q = 0; q < Q_; q++) {
        float s = 0.f;
#pragma unroll
        for (int p = 0; p < P_; p++) s += vals[p] * Ts[p][q];
        op[(long)q * N_ * F_] = roundtf(s);
    }
}

// ---------------- setup: transposed + rounded weights, c1 --------------------
__global__ __launch_bounds__(256) void prep_weights(const float* __restrict__ Win,
                                                    const float* __restrict__ Wq,
                                                    const float* __restrict__ Wk,
                                                    const float* __restrict__ Wv,
                                                    const float* __restrict__ Wout) {
    int i = blockIdx.x * blockDim.x + threadIdx.x;
    if (i < D_ * D_) {
        int r = i / D_, c = i % D_;
        g_WqkvT[(long)c * D_ + r]            = roundtf(Wq[i] * 0.0625f);
        g_WqkvT[(long)(D_ + c) * D_ + r]     = roundtf(Wk[i]);
        g_WqkvT[(long)(2 * D_ + c) * D_ + r] = roundtf(Wv[i]);
    }
    if (i < F_ * D_) {
        int r = i / D_, c = i % D_;
        g_WinT[(long)c * F_ + r] = roundtf(Win[i]);
    }
    if (i < D_ * F_) {
        int r = i / F_, c = i % F_;
        g_WoutT[(long)c * D_ + r] = roundtf(Wout[i]);
    }
}

__global__ __launch_bounds__(256) void scaleA_kernel(const float* __restrict__ A) {
    int i = blockIdx.x * blockDim.x + threadIdx.x;
    if (i < N_ * N_) g_CP[i] = roundtf(DT_ * A[i]);
}

// ---------------- rowsum: fac[row] = 1 / sum(exp'd scores) -------------------
// One warp per 512-wide row; read-only pass over S.
__global__ __launch_bounds__(256) void rowsum_kernel() {
    long row = (long)blockIdx.x * 8 + (threadIdx.x >> 5);
    int lane = threadIdx.x & 31;
    if (row >= (long)NBQ * N_) return;
    const float4* p = (const float4*)(g_S + row * N_);
    float s = 0.f;
#pragma unroll
    for (int i = 0; i < 4; i++) {
        float4 v = p[lane + i * 32];
        s += (v.x + v.y) + (v.z + v.w);
    }
#pragma unroll
    for (int o = 16; o; o >>= 1) s += __shfl_xor_sync(0xffffffffu, s, o);
    if (lane == 0) g_fac[row] = 1.f / s;
}

// ---------------- tf32 tensor-core GEMM: cp.async x3 + ldmatrix, BK=32 -------
// C = op_epi(alpha*A*op(B)) + beta*R (RESID) + R2[row%512] (RESID2)
// EXPC: epilogue applies __expf (softmax numerator; max-free is exact here).
// FAC:  A fragments scaled by fac[bz*M + row] before tf32 cvt (softmax denom).
template <int BM, int BN, int WM, int WN, bool TRANS_B, bool RESID, int RMOD,
          bool CVT_A, bool CVT_B, bool ROUND_C, bool RESID2, bool EXPC, bool FAC,
          int KBT, int OCC>
__global__ __launch_bounds__(WM* WN * 32, OCC) void gemm_tc(
    const float* __restrict__ A, const float* __restrict__ Bm,
    float* __restrict__ C, const float* __restrict__ R,
    const float* __restrict__ R2, const float* __restrict__ fac,
    int M, int Nn, int K, int lda, int ldb, int ldc, int ldr,
    long sA, long sB, long sC, long sR, float alpha, float beta) {
    constexpr int STAGES = 3;
    constexpr int NTH = WM * WN * 32;
    constexpr int WTM = BM / WM;           // 64
    constexpr int WTN = BN / WN;           // 32
    constexpr int FM = WTM / 16;           // 4
    constexpr int FN = WTN / 8;            // 4
    constexpr int KQ = KBT / 4;            // 16B chunks per row (8)
    constexpr int LDA_S = KBT + 4;         // 36 words: conflict-free
    constexpr int LDB_S = BN + 8;
    constexpr int NA = BM * KBT / (4 * NTH);
    constexpr int NB = BN * KBT / (4 * NTH);
    constexpr int A_STAGE_B = BM * LDA_S * 4;
    constexpr int BT_STAGE_B = BN * LDA_S * 4;
    constexpr int BN_STAGE_B = KBT * LDB_S * 4;

    extern __shared__ __align__(16) float smem[];
    float* Bs_ = smem + STAGES * BM * LDA_S;
    const uint32_t smem_u32 = (uint32_t)__cvta_generic_to_shared(smem);
    const uint32_t bs_u32 = smem_u32 + STAGES * A_STAGE_B;

    const int bz = blockIdx.z;
    A += (long)bz * sA;
    Bm += (long)bz * sB;
    C += (long)bz * sC;
    if (RESID) R += (long)bz * sR;

    const int row0 = blockIdx.y * BM, col0 = blockIdx.x * BN;
    const int tid = threadIdx.x;
    const int lane = tid & 31, wid = tid >> 5;
    const int grp = lane >> 2, qid = lane & 3;
    const int wm = wid / WN, wn = wid % WN;
    const int m_base = wm * WTM, n_base = wn * WTN;

    const int mi = lane >> 3, rr = lane & 7;
    const uint32_t aAddr0 = smem_u32 +
        (((m_base + ((mi & 1) << 3) + rr) * LDA_S + ((mi >> 1) << 2)) << 2);
    const uint32_t bAddr0 = bs_u32 +
        (((n_base + ((mi >> 1) << 3) + rr) * LDA_S + ((mi & 1) << 2)) << 2);

    float acc[FM][FN][4] = {};
    float facr[FM][2];
    if (FAC) {   // one factor per output row, constant over k
        const float* fb = fac + (long)bz * M + row0 + m_base + grp;
#pragma unroll
        for (int i = 0; i < FM; i++) {
            facr[i][0] = fb[i * 16];
            facr[i][1] = fb[i * 16 + 8];
        }
    }

    auto issue = [&](int st, int k0) {
#pragma unroll
        for (int l = 0; l < NA; l++) {
            int i = tid + l * NTH;
            int r = i / KQ, kq = i % KQ;
            cp_async16(smem_u32 + st * A_STAGE_B + ((r * LDA_S + kq * 4) << 2),
                       A + (long)(row0 + r) * lda + k0 + kq * 4);
        }
#pragma unroll
        for (int l = 0; l < NB; l++) {
            int i = tid + l * NTH;
            if (!TRANS_B) {
                int kk = i / (BN / 4), nq = i % (BN / 4);
                cp_async16(bs_u32 + st * BN_STAGE_B + ((kk * LDB_S + nq * 4) << 2),
                           Bm + (long)(k0 + kk) * ldb + col0 + nq * 4);
            } else {
                int n = i / KQ, kq = i % KQ;
                cp_async16(bs_u32 + st * BT_STAGE_B + ((n * LDA_S + kq * 4) << 2),
                           Bm + (long)(col0 + n) * ldb + k0 + kq * 4);
            }
        }
    };

    const int kt = K / KBT;
#pragma unroll
    for (int s = 0; s < STAGES - 1; s++) {
        issue(s, s * KBT);
        asm volatile("cp.async.commit_group;\n");
    }

    for (int t = 0; t < kt; t++) {
        asm volatile("cp.async.wait_group %0;\n" :: "n"(STAGES - 2));
        __syncthreads();
        const int st = t % STAGES;
        const int nx = t + STAGES - 1;
        if (nx < kt) issue(nx % STAGES, nx * KBT);
        asm volatile("cp.async.commit_group;\n");

        const uint32_t aSt = aAddr0 + st * A_STAGE_B;
        const uint32_t bSt = bAddr0 + st * BT_STAGE_B;

#pragma unroll
        for (int kc = 0; kc < KBT / 8; kc++) {
            const int kk = kc * 8;
            uint32_t af[FM][4], bf[FN][2];
#pragma unroll
            for (int i = 0; i < FM; i++) {
                ldsm_x4(af[i], aSt + i * (16 * LDA_S * 4) + kc * 32);
                if (FAC) {
                    af[i][0] = f2tf32(__uint_as_float(af[i][0]) * facr[i][0]);
                    af[i][1] = f2tf32(__uint_as_float(af[i][1]) * facr[i][1]);
                    af[i][2] = f2tf32(__uint_as_float(af[i][2]) * facr[i][0]);
                    af[i][3] = f2tf32(__uint_as_float(af[i][3]) * facr[i][1]);
                } else if (CVT_A) {
#pragma unroll
                    for (int q = 0; q < 4; q++) af[i][q] = f2tf32(__uint_as_float(af[i][q]));
                }
            }
            if (TRANS_B) {
#pragma unroll
                for (int jp = 0; jp < FN / 2; jp++) {
                    uint32_t tmp4[4];
                    ldsm_x4(tmp4, bSt + jp * (16 * LDA_S * 4) + kc * 32);
                    if (CVT_B) {
#pragma unroll
                        for (int q = 0; q < 4; q++) tmp4[q] = f2tf32(__uint_as_float(tmp4[q]));
                    }
                    bf[jp * 2][0] = tmp4[0]; bf[jp * 2][1] = tmp4[1];
                    bf[jp * 2 + 1][0] = tmp4[2]; bf[jp * 2 + 1][1] = tmp4[3];
                }
            } else {
#pragma unroll
                for (int j = 0; j < FN; j++) {
                    int n = n_base + j * 8 + grp;
                    float b0 = Bs_[(st * KBT + kk + qid) * LDB_S + n];
                    float b1 = Bs_[(st * KBT + kk + qid + 4) * LDB_S + n];
                    bf[j][0] = CVT_B ? f2tf32(b0) : __float_as_uint(b0);
                    bf[j][1] = CVT_B ? f2tf32(b1) : __float_as_uint(b1);
                }
            }
#pragma unroll
            for (int i = 0; i < FM; i++)
#pragma unroll
                for (int j = 0; j < FN; j++) mma_tf32(acc[i][j], af[i], bf[j]);
        }
    }

    // ---- epilogue ----
#pragma unroll
    for (int i = 0; i < FM; i++) {
        int r0 = row0 + m_base + i * 16 + grp;
#pragma unroll
        for (int j = 0; j < FN; j++) {
            int c = col0 + n_base + j * 8 + qid * 2;
            float2 v0 = {acc[i][j][0] * alpha, acc[i][j][1] * alpha};
            float2 v1 = {acc[i][j][2] * alpha, acc[i][j][3] * alpha};
            if (EXPC) {
                v0.x = __expf(v0.x); v0.y = __expf(v0.y);
                v1.x = __expf(v1.x); v1.y = __expf(v1.y);
            }
            if (RESID) {
                int rr0 = RMOD ? (r0 % RMOD) : r0;
                int rr1 = RMOD ? ((r0 + 8) % RMOD) : (r0 + 8);
                float2 r0v = *(const float2*)(R + (long)rr0 * ldr + c);
                float2 r1v = *(const float2*)(R + (long)rr1 * ldr + c);
                v0.x += beta * r0v.x; v0.y += beta * r0v.y;
                v1.x += beta * r1v.x; v1.y += beta * r1v.y;
            }
            if (RESID2) {
                float2 a0 = *(const float2*)(R2 + (long)(r0 % N_) * N_ + c);
                float2 a1 = *(const float2*)(R2 + (long)((r0 + 8) % N_) * N_ + c);
                v0.x += a0.x; v0.y += a0.y;
                v1.x += a1.x; v1.y += a1.y;
            }
            if (ROUND_C) {
                v0.x = roundtf(v0.x); v0.y = roundtf(v0.y);
                v1.x = roundtf(v1.x); v1.y = roundtf(v1.y);
            }
            *(float2*)(C + (long)r0 * ldc + c) = v0;
            *(float2*)(C + (long)(r0 + 8) * ldc + c) = v1;
        }
    }
}

// host-side smem size mirror (BK=32, 3 stages)
static inline int gemm_smem_bytes(int BM, int BN, bool transB) {
    const int STAGES = 3, KBT = 32, LDA_S = KBT + 4;
    int a = STAGES * BM * LDA_S;
    int b = transB ? STAGES * BN * LDA_S : STAGES * KBT * (BN + 8);
    return (a + b) * 4;
}

// ---------------- launch ----------------------------------------------------
extern "C" void kernel_launch(void* const* d_in, const int* in_sizes, int n_in,
                              void* d_out, int out_size) {
    const float* inputs = (const float*)d_in[0];
    const float* W_in  = (const float*)d_in[2];
    const float* T_mix = (const float*)d_in[3];
    const float* Wq    = (const float*)d_in[4];
    const float* Wk    = (const float*)d_in[5];
    const float* Wv    = (const float*)d_in[6];
    const float* W_out = (const float*)d_in[7];
    const float* A     = (const float*)d_in[8];

    float* out = (float*)d_out;
    float* mgt = out;
    float* kal = out + (long)B_ * Q_ * N_ * F_;

    float *tmp, *h, *qkv, *S, *CP, *WinT, *WqkvT, *WoutT, *fac;
    cudaGetSymbolAddress((void**)&tmp, g_tmp);
    cudaGetSymbolAddress((void**)&h, g_h);
    cudaGetSymbolAddress((void**)&qkv, g_qkv);
    cudaGetSymbolAddress((void**)&S, g_S);
    cudaGetSymbolAddress((void**)&CP, g_CP);
    cudaGetSymbolAddress((void**)&WinT, g_WinT);
    cudaGetSymbolAddress((void**)&WqkvT, g_WqkvT);
    cudaGetSymbolAddress((void**)&WoutT, g_WoutT);
    cudaGetSymbolAddress((void**)&fac, g_fac);

    const long sNN = (long)N_ * N_;
    const long sNF = (long)N_ * F_;
    const long sQKV = (long)N_ * 3 * D_;
    const long sH = (long)N_ * D_;

    // GEMM instances: BN=128, warp tile 64x32, 2 CTAs/SM, BK=32
    auto kNT  = gemm_tc<128, 128, 2, 4, true,  false, 0,  false, false, true,  false, false, false, 32, 2>;
    auto kQK  = gemm_tc<128, 128, 2, 4, true,  false, 0,  false, false, false, false, true,  false, 32, 2>;
    auto kAV  = gemm_tc<128, 128, 2, 4, false, true,  0,  false, false, true,  false, false, true,  32, 2>;
    auto kOUT = gemm_tc<128, 64,  2, 2, true,  false, 0,  false, false, false, false, false, false, 32, 2>;
    auto kCP  = gemm_tc<128, 128, 2, 4, false, true,  0,  false, false, true,  true,  false, false, 32, 2>;
    auto kKAL = gemm_tc<128, 64,  2, 2, false, true,  N_, false, true,  false, false, false, false, 32, 2>;

    const int smNT   = gemm_smem_bytes(128, 128, true);
    const int smNN   = gemm_smem_bytes(128, 128, false);
    const int smNT64 = gemm_smem_bytes(128, 64, true);
    const int smNN64 = gemm_smem_bytes(128, 64, false);
    cudaFuncSetAttribute(kNT,  cudaFuncAttributeMaxDynamicSharedMemorySize, smNT);
    cudaFuncSetAttribute(kQK,  cudaFuncAttributeMaxDynamicSharedMemorySize, smNT);
    cudaFuncSetAttribute(kAV,  cudaFuncAttributeMaxDynamicSharedMemorySize, smNN);
    cudaFuncSetAttribute(kOUT, cudaFuncAttributeMaxDynamicSharedMemorySize, smNT64);
    cudaFuncSetAttribute(kCP,  cudaFuncAttributeMaxDynamicSharedMemorySize, smNN);
    cudaFuncSetAttribute(kKAL, cudaFuncAttributeMaxDynamicSharedMemorySize, smNN64);

    // K1 + setup
    mix_kernel<<<((long)B_ * N_ * F_ + 255) / 256, 256>>>(inputs, T_mix);
    prep_weights<<<(D_ * D_ + 255) / 256, 256>>>(W_in, Wq, Wk, Wv, W_out);
    scaleA_kernel<<<(N_ * N_ + 255) / 256, 256>>>(A);   // c1 = tf32(DT*A)

    // CP chain: c_{k+j} = c_k @ c_j + c_k + c_j  (log-depth, 4 launches)
    float* c1 = CP;
    float* c2 = CP + sNN;
    float* c4 = CP + 3 * sNN;
    float* c8 = CP + 7 * sNN;
    kCP<<<dim3(4, 4, 1), 256, smNN>>>(c1, c1, c2, c1, c1, nullptr,
        N_, N_, N_, N_, N_, N_, N_, 0, 0, 0, 0, 1.f, 1.f);
    kCP<<<dim3(4, 8, 1), 256, smNN>>>(CP, c2, CP + 2 * sNN, CP, c2, nullptr,
        2 * N_, N_, N_, N_, N_, N_, N_, 0, 0, 0, 0, 1.f, 1.f);
    kCP<<<dim3(4, 16, 1), 256, smNN>>>(CP, c4, CP + 4 * sNN, CP, c4, nullptr,
        4 * N_, N_, N_, N_, N_, N_, N_, 0, 0, 0, 0, 1.f, 1.f);
    kCP<<<dim3(4, 16, 1), 256, smNN>>>(CP, c8, CP + 8 * sNN, CP, c8, nullptr,
        4 * N_, N_, N_, N_, N_, N_, N_, 0, 0, 0, 0, 1.f, 1.f);

    // K2: h = tmp @ WinT^T
    kNT<<<dim3(2, BQN / 128, 1), 256, smNT>>>(
        tmp, WinT, h, nullptr, nullptr, nullptr,
        BQN, D_, F_, F_, F_, D_, 0, 0, 0, 0, 0, 1.f, 0.f);

    // K3: qkv = h @ WqkvT^T
    kNT<<<dim3(6, BQN / 128, 1), 256, smNT>>>(
        h, WqkvT, qkv, nullptr, nullptr, nullptr,
        BQN, 3 * D_, D_, D_, D_, 3 * D_, 0, 0, 0, 0, 0, 1.f, 0.f);

    // K4: S = exp(q @ k^T)  batched (NT) — max-free softmax numerator
    kQK<<<dim3(4, 4, NBQ), 256, smNT>>>(
        qkv, qkv + D_, S, nullptr, nullptr, nullptr,
        N_, N_, D_, 3 * D_, 3 * D_, N_, 0, sQKV, sQKV, sNN, 0, 1.f, 0.f);

    // K5: fac = 1 / rowsum(S)   (read-only pass)
    rowsum_kernel<<<((long)NBQ * N_ + 7) / 8, 256>>>();

    // K6: h = h + (S * fac[row]) @ v  batched (NN, residual)
    kAV<<<dim3(2, 4, NBQ), 256, smNN>>>(
        S, qkv + 2 * D_, h, h, nullptr, fac,
        N_, D_, N_, N_, 3 * D_, D_, D_, sNN, sQKV, sH, sH, 1.f, 1.f);

    // K7: mgt = h @ WoutT^T
    kOUT<<<dim3(1, BQN / 128, 1), 128, smNT64>>>(
        h, WoutT, mgt, nullptr, nullptr, nullptr,
        BQN, F_, D_, D_, D_, F_, 0, 0, 0, 0, 0, 1.f, 0.f);

    // Kalman (single parallel launch): kal[b, t] = c_{t+1} @ mu0[b] + mu0[b]
    const float* mu0 = inputs + (long)(P_ - 1) * sNF;
    kKAL<<<dim3(1, 12 * N_ / 128, B_), 128, smNN64>>>(
        CP, mu0, kal, mu0, nullptr, nullptr,
        12 * N_, F_, N_, N_, F_, F_, F_,
        0, (long)P_ * sNF, (long)Q_ * sNF, (long)P_ * sNF, 1.f, 1.f);
}

// round 11
// speedup vs baseline: 1.0414x; 1.0414x over previous
#include <cuda_runtime.h>
#include <cstdint>

// Problem dims
#define B_ 32
#define P_ 12
#define N_ 512
#define F_ 64
#define D_ 256
#define Q_ 12
#define DT_ 0.1f

static const int BQN = B_ * Q_ * N_;  // 196608
#define NBQ (B_ * Q_)                 // 384

// ---------------- scratch (device globals; no runtime alloc) ----------------
__device__ float g_tmp  [(size_t)B_ * Q_ * N_ * F_];     // mixed inputs (tf32 bits)
__device__ float g_h    [(size_t)B_ * Q_ * N_ * D_];     // hidden (tf32 bits)
__device__ float g_qkv  [(size_t)B_ * Q_ * N_ * 3 * D_]; // q|k|v, ld=768 (tf32 bits)
__device__ float g_S    [(size_t)B_ * Q_ * N_ * N_];     // exp'd scores (fp32)
__device__ float g_CP   [(size_t)12 * N_ * N_];          // c_k = (I+DT*A)^k - I, tf32
__device__ float g_WinT [(size_t)D_ * F_];               // W_in^T  tf32
__device__ float g_WqkvT[(size_t)3 * D_ * D_];           // Wqkv^T  tf32
__device__ float g_WoutT[(size_t)F_ * D_];               // W_out^T tf32
__device__ float g_fac  [(size_t)NBQ * N_];              // rowsum(exp scores), atomic

// ---------------- helpers ----------------------------------------------------
__device__ __forceinline__ uint32_t f2tf32(float f) {
    uint32_t u;
    asm("cvt.rna.tf32.f32 %0, %1;" : "=r"(u) : "f"(f));
    return u;
}
__device__ __forceinline__ float roundtf(float f) { return __uint_as_float(f2tf32(f)); }

__device__ __forceinline__ void mma_tf32(float* c, const uint32_t* a, const uint32_t* b) {
    asm volatile(
        "mma.sync.aligned.m16n8k8.row.col.f32.tf32.tf32.f32 "
        "{%0,%1,%2,%3}, {%4,%5,%6,%7}, {%8,%9}, {%0,%1,%2,%3};"
        : "+f"(c[0]), "+f"(c[1]), "+f"(c[2]), "+f"(c[3])
        : "r"(a[0]), "r"(a[1]), "r"(a[2]), "r"(a[3]),
          "r"(b[0]), "r"(b[1]));
}

__device__ __forceinline__ void ldsm_x4(uint32_t* r, uint32_t addr) {
    asm volatile("ldmatrix.sync.aligned.m8n8.x4.shared.b16 {%0,%1,%2,%3}, [%4];"
                 : "=r"(r[0]), "=r"(r[1]), "=r"(r[2]), "=r"(r[3]) : "r"(addr));
}

__device__ __forceinline__ void cp_async16(uint32_t smem_dst, const void* gsrc) {
    asm volatile("cp.async.cg.shared.global [%0], [%1], 16;\n" :: "r"(smem_dst), "l"(gsrc));
}

// ---------------- K0: fused setup --------------------------------------------
// time-mix (tf32), transposed+rounded weights, c1 = tf32(DT*A), fac = 0.
__global__ __launch_bounds__(256) void setup_kernel(const float* __restrict__ in,
                                                    const float* __restrict__ T,
                                                    const float* __restrict__ Win,
                                                    const float* __restrict__ Wq,
                                                    const float* __restrict__ Wk,
                                                    const float* __restrict__ Wv,
                                                    const float* __restrict__ Wout,
                                                    const float* __restrict__ A) {
    __shared__ float Ts[P_][Q_];
    int t = threadIdx.x;
    if (t < P_ * Q_) Ts[t / Q_][t % Q_] = T[t];
    long idx = (long)blockIdx.x * 256 + t;

    if (idx < (long)D_ * D_) {      // Wq/Wk/Wv transpose into WqkvT rows
        int r = (int)(idx / D_), c = (int)(idx % D_);
        g_WqkvT[(long)c * D_ + r]            = roundtf(Wq[idx] * 0.0625f);
        g_WqkvT[(long)(D_ + c) * D_ + r]     = roundtf(Wk[idx]);
        g_WqkvT[(long)(2 * D_ + c) * D_ + r] = roundtf(Wv[idx]);
    }
    if (idx < (long)F_ * D_) {      // W_in (F x D) -> WinT (D x F)
        int r = (int)(idx / D_), c = (int)(idx % D_);
        g_WinT[(long)c * F_ + r] = roundtf(Win[idx]);
    }
    if (idx < (long)D_ * F_) {      // W_out (D x F) -> WoutT (F x D)
        int r = (int)(idx / F_), c = (int)(idx % F_);
        g_WoutT[(long)c * D_ + r] = roundtf(Wout[idx]);
    }
    if (idx < (long)N_ * N_) g_CP[idx] = roundtf(DT_ * A[idx]);
    if (idx < (long)NBQ * N_) g_fac[idx] = 0.f;

    __syncthreads();   // Ts ready
    if (idx < (long)B_ * N_ * F_) {
        int f = (int)(idx % F_);
        int n = (int)((idx / F_) % N_);
        int b = (int)(idx / ((long)F_ * N_));
        float vals[P_];
        const float* ip = in + ((long)b * P_ * N_ + n) * F_ + f;
#pragma unroll
        for (int p = 0; p < P_; p++) vals[p] = ip[(long)p * N_ * F_];
        float* op = g_tmp + ((long)b * Q_ * N_ + n) * F_ + f;
#pragma unroll
        for (int q = 0; q < Q_; q++) {
            float s = 0.f;
#pragma unroll
            for (int p = 0; p < P_; p++) s += vals[p] * Ts[p][q];
            op[(long)q * N_ * F_] = roundtf(s);
        }
    }
}

// ---------------- tf32 tensor-core GEMM: cp.async x3 + ldmatrix, BK=32 -------
// C = op_epi(alpha*A*op(B)) + beta*R (RESID) + R2[row%512] (RESID2)
// EXPC: epilogue applies __expf (max-free softmax numerator — exact here).
// SUMS: epilogue atomically accumulates per-row sums of stored values into fac.
// FAC:  A fragments scaled by 1/fac[bz*M+row] before tf32 cvt (softmax denom).
template <int BM, int BN, int WM, int WN, bool TRANS_B, bool RESID, int RMOD,
          bool CVT_A, bool CVT_B, bool ROUND_C, bool RESID2, bool EXPC, bool FAC,
          bool SUMS, int KBT, int OCC>
__global__ __launch_bounds__(WM* WN * 32, OCC) void gemm_tc(
    const float* __restrict__ A, const float* __restrict__ Bm,
    float* __restrict__ C, const float* __restrict__ R,
    const float* __restrict__ R2, float* __restrict__ fac,
    int M, int Nn, int K, int lda, int ldb, int ldc, int ldr,
    long sA, long sB, long sC, long sR, float alpha, float beta) {
    constexpr int STAGES = 3;
    constexpr int NTH = WM * WN * 32;
    constexpr int WTM = BM / WM;           // 64
    constexpr int WTN = BN / WN;           // 32
    constexpr int FM = WTM / 16;           // 4
    constexpr int FN = WTN / 8;            // 4
    constexpr int KQ = KBT / 4;            // 16B chunks per row (8)
    constexpr int LDA_S = KBT + 4;         // 36 words: conflict-free
    constexpr int LDB_S = BN + 8;
    constexpr int NA = BM * KBT / (4 * NTH);
    constexpr int NB = BN * KBT / (4 * NTH);
    constexpr int A_STAGE_B = BM * LDA_S * 4;
    constexpr int BT_STAGE_B = BN * LDA_S * 4;
    constexpr int BN_STAGE_B = KBT * LDB_S * 4;

    extern __shared__ __align__(16) float smem[];
    float* Bs_ = smem + STAGES * BM * LDA_S;
    const uint32_t smem_u32 = (uint32_t)__cvta_generic_to_shared(smem);
    const uint32_t bs_u32 = smem_u32 + STAGES * A_STAGE_B;

    const int bz = blockIdx.z;
    A += (long)bz * sA;
    Bm += (long)bz * sB;
    C += (long)bz * sC;
    if (RESID) R += (long)bz * sR;

    const int row0 = blockIdx.y * BM, col0 = blockIdx.x * BN;
    const int tid = threadIdx.x;
    const int lane = tid & 31, wid = tid >> 5;
    const int grp = lane >> 2, qid = lane & 3;
    const int wm = wid / WN, wn = wid % WN;
    const int m_base = wm * WTM, n_base = wn * WTN;

    const int mi = lane >> 3, rr = lane & 7;
    const uint32_t aAddr0 = smem_u32 +
        (((m_base + ((mi & 1) << 3) + rr) * LDA_S + ((mi >> 1) << 2)) << 2);
    const uint32_t bAddr0 = bs_u32 +
        (((n_base + ((mi >> 1) << 3) + rr) * LDA_S + ((mi & 1) << 2)) << 2);

    float acc[FM][FN][4] = {};
    float facr[FM][2];
    if (FAC) {   // reciprocal of accumulated row sums; constant over k
        const float* fb = fac + (long)bz * M + row0 + m_base + grp;
#pragma unroll
        for (int i = 0; i < FM; i++) {
            facr[i][0] = 1.f / fb[i * 16];
            facr[i][1] = 1.f / fb[i * 16 + 8];
        }
    }

    auto issue = [&](int st, int k0) {
#pragma unroll
        for (int l = 0; l < NA; l++) {
            int i = tid + l * NTH;
            int r = i / KQ, kq = i % KQ;
            cp_async16(smem_u32 + st * A_STAGE_B + ((r * LDA_S + kq * 4) << 2),
                       A + (long)(row0 + r) * lda + k0 + kq * 4);
        }
#pragma unroll
        for (int l = 0; l < NB; l++) {
            int i = tid + l * NTH;
            if (!TRANS_B) {
                int kk = i / (BN / 4), nq = i % (BN / 4);
                cp_async16(bs_u32 + st * BN_STAGE_B + ((kk * LDB_S + nq * 4) << 2),
                           Bm + (long)(k0 + kk) * ldb + col0 + nq * 4);
            } else {
                int n = i / KQ, kq = i % KQ;
                cp_async16(bs_u32 + st * BT_STAGE_B + ((n * LDA_S + kq * 4) << 2),
                           Bm + (long)(col0 + n) * ldb + k0 + kq * 4);
            }
        }
    };

    const int kt = K / KBT;
#pragma unroll
    for (int s = 0; s < STAGES - 1; s++) {
        issue(s, s * KBT);
        asm volatile("cp.async.commit_group;\n");
    }

    for (int t = 0; t < kt; t++) {
        asm volatile("cp.async.wait_group %0;\n" :: "n"(STAGES - 2));
        __syncthreads();
        const int st = t % STAGES;
        const int nx = t + STAGES - 1;
        if (nx < kt) issue(nx % STAGES, nx * KBT);
        asm volatile("cp.async.commit_group;\n");

        const uint32_t aSt = aAddr0 + st * A_STAGE_B;
        const uint32_t bSt = bAddr0 + st * BT_STAGE_B;

#pragma unroll
        for (int kc = 0; kc < KBT / 8; kc++) {
            const int kk = kc * 8;
            uint32_t af[FM][4], bf[FN][2];
#pragma unroll
            for (int i = 0; i < FM; i++) {
                ldsm_x4(af[i], aSt + i * (16 * LDA_S * 4) + kc * 32);
                if (FAC) {
                    af[i][0] = f2tf32(__uint_as_float(af[i][0]) * facr[i][0]);
                    af[i][1] = f2tf32(__uint_as_float(af[i][1]) * facr[i][1]);
                    af[i][2] = f2tf32(__uint_as_float(af[i][2]) * facr[i][0]);
                    af[i][3] = f2tf32(__uint_as_float(af[i][3]) * facr[i][1]);
                } else if (CVT_A) {
#pragma unroll
                    for (int q = 0; q < 4; q++) af[i][q] = f2tf32(__uint_as_float(af[i][q]));
                }
            }
            if (TRANS_B) {
#pragma unroll
                for (int jp = 0; jp < FN / 2; jp++) {
                    uint32_t tmp4[4];
                    ldsm_x4(tmp4, bSt + jp * (16 * LDA_S * 4) + kc * 32);
                    if (CVT_B) {
#pragma unroll
                        for (int q = 0; q < 4; q++) tmp4[q] = f2tf32(__uint_as_float(tmp4[q]));
                    }
                    bf[jp * 2][0] = tmp4[0]; bf[jp * 2][1] = tmp4[1];
                    bf[jp * 2 + 1][0] = tmp4[2]; bf[jp * 2 + 1][1] = tmp4[3];
                }
            } else {
#pragma unroll
                for (int j = 0; j < FN; j++) {
                    int n = n_base + j * 8 + grp;
                    float b0 = Bs_[(st * KBT + kk + qid) * LDB_S + n];
                    float b1 = Bs_[(st * KBT + kk + qid + 4) * LDB_S + n];
                    bf[j][0] = CVT_B ? f2tf32(b0) : __float_as_uint(b0);
                    bf[j][1] = CVT_B ? f2tf32(b1) : __float_as_uint(b1);
                }
            }
#pragma unroll
            for (int i = 0; i < FM; i++)
#pragma unroll
                for (int j = 0; j < FN; j++) mma_tf32(acc[i][j], af[i], bf[j]);
        }
    }

    // ---- epilogue ----
    float rs[FM][2];
    if (SUMS) {
#pragma unroll
        for (int i = 0; i < FM; i++) { rs[i][0] = 0.f; rs[i][1] = 0.f; }
    }
#pragma unroll
    for (int i = 0; i < FM; i++) {
        int r0 = row0 + m_base + i * 16 + grp;
#pragma unroll
        for (int j = 0; j < FN; j++) {
            int c = col0 + n_base + j * 8 + qid * 2;
            float2 v0 = {acc[i][j][0] * alpha, acc[i][j][1] * alpha};
            float2 v1 = {acc[i][j][2] * alpha, acc[i][j][3] * alpha};
            if (EXPC) {
                v0.x = __expf(v0.x); v0.y = __expf(v0.y);
                v1.x = __expf(v1.x); v1.y = __expf(v1.y);
            }
            if (SUMS) {
                rs[i][0] += v0.x + v0.y;
                rs[i][1] += v1.x + v1.y;
            }
            if (RESID) {
                int rr0 = RMOD ? (r0 % RMOD) : r0;
                int rr1 = RMOD ? ((r0 + 8) % RMOD) : (r0 + 8);
                float2 r0v = *(const float2*)(R + (long)rr0 * ldr + c);
                float2 r1v = *(const float2*)(R + (long)rr1 * ldr + c);
                v0.x += beta * r0v.x; v0.y += beta * r0v.y;
                v1.x += beta * r1v.x; v1.y += beta * r1v.y;
            }
            if (RESID2) {
                float2 a0 = *(const float2*)(R2 + (long)(r0 % N_) * N_ + c);
                float2 a1 = *(const float2*)(R2 + (long)((r0 + 8) % N_) * N_ + c);
                v0.x += a0.x; v0.y += a0.y;
                v1.x += a1.x; v1.y += a1.y;
            }
            if (ROUND_C) {
                v0.x = roundtf(v0.x); v0.y = roundtf(v0.y);
                v1.x = roundtf(v1.x); v1.y = roundtf(v1.y);
            }
            *(float2*)(C + (long)r0 * ldc + c) = v0;
            *(float2*)(C + (long)(r0 + 8) * ldc + c) = v1;
        }
    }
    if (SUMS) {   // quad-reduce covers this warp's 32 cols; atomics combine rest
#pragma unroll
        for (int i = 0; i < FM; i++)
#pragma unroll
            for (int h = 0; h < 2; h++) {
                float s = rs[i][h];
                s += __shfl_xor_sync(0xffffffffu, s, 1);
                s += __shfl_xor_sync(0xffffffffu, s, 2);
                if (qid == 0)
                    atomicAdd(fac + (long)bz * M + row0 + m_base + i * 16 + grp + h * 8, s);
            }
    }
}

// host-side smem size mirror (BK=32, 3 stages)
static inline int gemm_smem_bytes(int BM, int BN, bool transB) {
    const int STAGES = 3, KBT = 32, LDA_S = KBT + 4;
    int a = STAGES * BM * LDA_S;
    int b = transB ? STAGES * BN * LDA_S : STAGES * KBT * (BN + 8);
    return (a + b) * 4;
}

// ---------------- launch ----------------------------------------------------
extern "C" void kernel_launch(void* const* d_in, const int* in_sizes, int n_in,
                              void* d_out, int out_size) {
    const float* inputs = (const float*)d_in[0];
    const float* W_in  = (const float*)d_in[2];
    const float* T_mix = (const float*)d_in[3];
    const float* Wq    = (const float*)d_in[4];
    const float* Wk    = (const float*)d_in[5];
    const float* Wv    = (const float*)d_in[6];
    const float* W_out = (const float*)d_in[7];
    const float* A     = (const float*)d_in[8];

    float* out = (float*)d_out;
    float* mgt = out;
    float* kal = out + (long)B_ * Q_ * N_ * F_;

    float *tmp, *h, *qkv, *S, *CP, *WinT, *WqkvT, *WoutT, *fac;
    cudaGetSymbolAddress((void**)&tmp, g_tmp);
    cudaGetSymbolAddress((void**)&h, g_h);
    cudaGetSymbolAddress((void**)&qkv, g_qkv);
    cudaGetSymbolAddress((void**)&S, g_S);
    cudaGetSymbolAddress((void**)&CP, g_CP);
    cudaGetSymbolAddress((void**)&WinT, g_WinT);
    cudaGetSymbolAddress((void**)&WqkvT, g_WqkvT);
    cudaGetSymbolAddress((void**)&WoutT, g_WoutT);
    cudaGetSymbolAddress((void**)&fac, g_fac);

    const long sNN = (long)N_ * N_;
    const long sNF = (long)N_ * F_;
    const long sQKV = (long)N_ * 3 * D_;
    const long sH = (long)N_ * D_;

    // GEMM instances: BN=128, warp tile 64x32, 2 CTAs/SM, BK=32
    auto kNT  = gemm_tc<128, 128, 2, 4, true,  false, 0,  false, false, true,  false, false, false, false, 32, 2>;
    auto kQK  = gemm_tc<128, 128, 2, 4, true,  false, 0,  false, false, false, false, true,  false, true,  32, 2>;
    auto kAV  = gemm_tc<128, 128, 2, 4, false, true,  0,  false, false, true,  false, false, true,  false, 32, 2>;
    auto kOUT = gemm_tc<128, 64,  2, 2, true,  false, 0,  false, false, false, false, false, false, false, 32, 2>;
    auto kCP  = gemm_tc<128, 128, 2, 4, false, true,  0,  false, false, true,  true,  false, false, false, 32, 2>;
    auto kKAL = gemm_tc<128, 64,  2, 2, false, true,  N_, false, true,  false, false, false, false, false, 32, 2>;

    const int smNT   = gemm_smem_bytes(128, 128, true);
    const int smNN   = gemm_smem_bytes(128, 128, false);
    const int smNT64 = gemm_smem_bytes(128, 64, true);
    const int smNN64 = gemm_smem_bytes(128, 64, false);
    cudaFuncSetAttribute(kNT,  cudaFuncAttributeMaxDynamicSharedMemorySize, smNT);
    cudaFuncSetAttribute(kQK,  cudaFuncAttributeMaxDynamicSharedMemorySize, smNT);
    cudaFuncSetAttribute(kAV,  cudaFuncAttributeMaxDynamicSharedMemorySize, smNN);
    cudaFuncSetAttribute(kOUT, cudaFuncAttributeMaxDynamicSharedMemorySize, smNT64);
    cudaFuncSetAttribute(kCP,  cudaFuncAttributeMaxDynamicSharedMemorySize, smNN);
    cudaFuncSetAttribute(kKAL, cudaFuncAttributeMaxDynamicSharedMemorySize, smNN64);

    // launch 0: fused setup (mix, weight prep, c1, fac=0)
    setup_kernel<<<((long)B_ * N_ * F_ + 255) / 256, 256>>>(
        inputs, T_mix, W_in, Wq, Wk, Wv, W_out, A);

    // launch 1 — K2: h = tmp @ WinT^T
    kNT<<<dim3(2, BQN / 128, 1), 256, smNT>>>(
        tmp, WinT, h, nullptr, nullptr, nullptr,
        BQN, D_, F_, F_, F_, D_, 0, 0, 0, 0, 0, 1.f, 0.f);

    // launch 2 — K3: qkv = h @ WqkvT^T
    kNT<<<dim3(6, BQN / 128, 1), 256, smNT>>>(
        h, WqkvT, qkv, nullptr, nullptr, nullptr,
        BQN, 3 * D_, D_, D_, D_, 3 * D_, 0, 0, 0, 0, 0, 1.f, 0.f);

    // launch 3 — K4: S = exp(q @ k^T), row sums accumulated into fac (profiled)
    kQK<<<dim3(4, 4, NBQ), 256, smNT>>>(
        qkv, qkv + D_, S, nullptr, nullptr, fac,
        N_, N_, D_, 3 * D_, 3 * D_, N_, 0, sQKV, sQKV, sNN, 0, 1.f, 0.f);

    // launch 4 — K6: h = h + (S / rowsum) @ v
    kAV<<<dim3(2, 4, NBQ), 256, smNN>>>(
        S, qkv + 2 * D_, h, h, nullptr, fac,
        N_, D_, N_, N_, 3 * D_, D_, D_, sNN, sQKV, sH, sH, 1.f, 1.f);

    // launch 5 — K7: mgt = h @ WoutT^T
    kOUT<<<dim3(1, BQN / 128, 1), 128, smNT64>>>(
        h, WoutT, mgt, nullptr, nullptr, nullptr,
        BQN, F_, D_, D_, D_, F_, 0, 0, 0, 0, 0, 1.f, 0.f);

    // CP chain (independent of MGT path; only feeds the final Kalman GEMM)
    float* c1 = CP;
    float* c2 = CP + sNN;
    float* c4 = CP + 3 * sNN;
    float* c8 = CP + 7 * sNN;
    kCP<<<dim3(4, 4, 1), 256, smNN>>>(c1, c1, c2, c1, c1, nullptr,
        N_, N_, N_, N_, N_, N_, N_, 0, 0, 0, 0, 1.f, 1.f);
    kCP<<<dim3(4, 8, 1), 256, smNN>>>(CP, c2, CP + 2 * sNN, CP, c2, nullptr,
        2 * N_, N_, N_, N_, N_, N_, N_, 0, 0, 0, 0, 1.f, 1.f);
    kCP<<<dim3(4, 16, 1), 256, smNN>>>(CP, c4, CP + 4 * sNN, CP, c4, nullptr,
        4 * N_, N_, N_, N_, N_, N_, N_, 0, 0, 0, 0, 1.f, 1.f);
    kCP<<<dim3(4, 16, 1), 256, smNN>>>(CP, c8, CP + 8 * sNN, CP, c8, nullptr,
        4 * N_, N_, N_, N_, N_, N_, N_, 0, 0, 0, 0, 1.f, 1.f);

    // Kalman (single parallel launch): kal[b, t] = c_{t+1} @ mu0[b] + mu0[b]
    const float* mu0 = inputs + (long)(P_ - 1) * sNF;
    kKAL<<<dim3(1, 12 * N_ / 128, B_), 128, smNN64>>>(
        CP, mu0, kal, mu0, nullptr, nullptr,
        12 * N_, F_, N_, N_, F_, F_, F_,
        0, (long)P_ * sNF, (long)Q_ * sNF, (long)P_ * sNF, 1.f, 1.f);
}

// round 12
// speedup vs baseline: 1.2787x; 1.2279x over previous
#include <cuda_runtime.h>
#include <cstdint>

// Problem dims
#define B_ 32
#define P_ 12
#define N_ 512
#define F_ 64
#define D_ 256
#define Q_ 12
#define DT_ 0.1f

static const int BQN = B_ * Q_ * N_;  // 196608
#define NBQ (B_ * Q_)                 // 384

// ---------------- scratch (device globals; no runtime alloc) ----------------
__device__ float g_tmp  [(size_t)B_ * Q_ * N_ * F_];     // mixed inputs (tf32 bits)
__device__ float g_h    [(size_t)B_ * Q_ * N_ * D_];     // hidden (tf32 bits)
__device__ float g_qkv  [(size_t)B_ * Q_ * N_ * 3 * D_]; // q|k|v, ld=768 (tf32 bits)
__device__ float g_S    [(size_t)B_ * Q_ * N_ * N_];     // exp'd scores (fp32)
__device__ float g_CP   [(size_t)12 * N_ * N_];          // c_k = (I+DT*A)^k - I, tf32
__device__ float g_WinT [(size_t)D_ * F_];               // W_in^T  (256x64)  tf32
__device__ float g_WqkvT[(size_t)3 * D_ * D_];           // Wqkv^T  (768x256) tf32
__device__ float g_WoutT[(size_t)F_ * D_];               // W_out^T (64x256)  tf32
__device__ float g_WcombT[(size_t)3 * D_ * F_];          // (W_in@Wqkv)^T (768x64) tf32
__device__ float g_fac  [(size_t)NBQ * N_];              // rowsum(exp scores), atomic

// ---------------- helpers ----------------------------------------------------
__device__ __forceinline__ uint32_t f2tf32(float f) {
    uint32_t u;
    asm("cvt.rna.tf32.f32 %0, %1;" : "=r"(u) : "f"(f));
    return u;
}
__device__ __forceinline__ float roundtf(float f) { return __uint_as_float(f2tf32(f)); }

__device__ __forceinline__ void mma_tf32(float* c, const uint32_t* a, const uint32_t* b) {
    asm volatile(
        "mma.sync.aligned.m16n8k8.row.col.f32.tf32.tf32.f32 "
        "{%0,%1,%2,%3}, {%4,%5,%6,%7}, {%8,%9}, {%0,%1,%2,%3};"
        : "+f"(c[0]), "+f"(c[1]), "+f"(c[2]), "+f"(c[3])
        : "r"(a[0]), "r"(a[1]), "r"(a[2]), "r"(a[3]),
          "r"(b[0]), "r"(b[1]));
}

__device__ __forceinline__ void ldsm_x4(uint32_t* r, uint32_t addr) {
    asm volatile("ldmatrix.sync.aligned.m8n8.x4.shared.b16 {%0,%1,%2,%3}, [%4];"
                 : "=r"(r[0]), "=r"(r[1]), "=r"(r[2]), "=r"(r[3]) : "r"(addr));
}

__device__ __forceinline__ void cp_async16(uint32_t smem_dst, const void* gsrc) {
    asm volatile("cp.async.cg.shared.global [%0], [%1], 16;\n" :: "r"(smem_dst), "l"(gsrc));
}

// ---------------- K0: fused setup --------------------------------------------
__global__ __launch_bounds__(256) void setup_kernel(const float* __restrict__ in,
                                                    const float* __restrict__ T,
                                                    const float* __restrict__ Win,
                                                    const float* __restrict__ Wq,
                                                    const float* __restrict__ Wk,
                                                    const float* __restrict__ Wv,
                                                    const float* __restrict__ Wout,
                                                    const float* __restrict__ A) {
    __shared__ float Ts[P_][Q_];
    int t = threadIdx.x;
    if (t < P_ * Q_) Ts[t / Q_][t % Q_] = T[t];
    long idx = (long)blockIdx.x * 256 + t;

    if (idx < (long)D_ * D_) {      // Wq/Wk/Wv transpose into WqkvT rows
        int r = (int)(idx / D_), c = (int)(idx % D_);
        g_WqkvT[(long)c * D_ + r]            = roundtf(Wq[idx] * 0.0625f);
        g_WqkvT[(long)(D_ + c) * D_ + r]     = roundtf(Wk[idx]);
        g_WqkvT[(long)(2 * D_ + c) * D_ + r] = roundtf(Wv[idx]);
    }
    if (idx < (long)F_ * D_) {      // W_in (F x D) -> WinT (D x F)
        int r = (int)(idx / D_), c = (int)(idx % D_);
        g_WinT[(long)c * F_ + r] = roundtf(Win[idx]);
    }
    if (idx < (long)D_ * F_) {      // W_out (D x F) -> WoutT (F x D)
        int r = (int)(idx / F_), c = (int)(idx % F_);
        g_WoutT[(long)c * D_ + r] = roundtf(Wout[idx]);
    }
    if (idx < (long)N_ * N_) g_CP[idx] = roundtf(DT_ * A[idx]);
    if (idx < (long)NBQ * N_) g_fac[idx] = 0.f;

    __syncthreads();   // Ts ready
    if (idx < (long)B_ * N_ * F_) {
        int f = (int)(idx % F_);
        int n = (int)((idx / F_) % N_);
        int b = (int)(idx / ((long)F_ * N_));
        float vals[P_];
        const float* ip = in + ((long)b * P_ * N_ + n) * F_ + f;
#pragma unroll
        for (int p = 0; p < P_; p++) vals[p] = ip[(long)p * N_ * F_];
        float* op = g_tmp + ((long)b * Q_ * N_ + n) * F_ + f;
#pragma unroll
        for (int q = 0; q < Q_; q++) {
            float s = 0.f;
#pragma unroll
            for (int p = 0; p < P_; p++) s += vals[p] * Ts[p][q];
            op[(long)q * N_ * F_] = roundtf(s);
        }
    }
}

// ---------------- tf32 tensor-core GEMM: cp.async x3 + ldmatrix, BK=32 -------
// C = op_epi(alpha*A*op(B)) + beta*R (RESID) + R2[row%512] (RESID2)
// EXPC: epilogue applies __expf (max-free softmax numerator — exact here).
// SUMS: epilogue atomically accumulates per-row sums of stored values into fac.
// FAC:  A fragments scaled by 1/fac[bz*M+row] before tf32 cvt (softmax denom).
template <int BM, int BN, int WM, int WN, bool TRANS_B, bool RESID, int RMOD,
          bool CVT_A, bool CVT_B, bool ROUND_C, bool RESID2, bool EXPC, bool FAC,
          bool SUMS, int KBT, int OCC>
__global__ __launch_bounds__(WM* WN * 32, OCC) void gemm_tc(
    const float* __restrict__ A, const float* __restrict__ Bm,
    float* __restrict__ C, const float* __restrict__ R,
    const float* __restrict__ R2, float* __restrict__ fac,
    int M, int Nn, int K, int lda, int ldb, int ldc, int ldr,
    long sA, long sB, long sC, long sR, float alpha, float beta) {
    constexpr int STAGES = 3;
    constexpr int NTH = WM * WN * 32;
    constexpr int WTM = BM / WM;           // 64
    constexpr int WTN = BN / WN;           // 32
    constexpr int FM = WTM / 16;           // 4
    constexpr int FN = WTN / 8;            // 4
    constexpr int KQ = KBT / 4;            // 16B chunks per row (8)
    constexpr int LDA_S = KBT + 4;         // 36 words: conflict-free
    constexpr int LDB_S = BN + 8;
    constexpr int NA = BM * KBT / (4 * NTH);
    constexpr int NB = BN * KBT / (4 * NTH);
    constexpr int A_STAGE_B = BM * LDA_S * 4;
    constexpr int BT_STAGE_B = BN * LDA_S * 4;
    constexpr int BN_STAGE_B = KBT * LDB_S * 4;

    extern __shared__ __align__(16) float smem[];
    float* Bs_ = smem + STAGES * BM * LDA_S;
    const uint32_t smem_u32 = (uint32_t)__cvta_generic_to_shared(smem);
    const uint32_t bs_u32 = smem_u32 + STAGES * A_STAGE_B;

    const int bz = blockIdx.z;
    A += (long)bz * sA;
    Bm += (long)bz * sB;
    C += (long)bz * sC;
    if (RESID) R += (long)bz * sR;

    const int row0 = blockIdx.y * BM, col0 = blockIdx.x * BN;
    const int tid = threadIdx.x;
    const int lane = tid & 31, wid = tid >> 5;
    const int grp = lane >> 2, qid = lane & 3;
    const int wm = wid / WN, wn = wid % WN;
    const int m_base = wm * WTM, n_base = wn * WTN;

    const int mi = lane >> 3, rr = lane & 7;
    const uint32_t aAddr0 = smem_u32 +
        (((m_base + ((mi & 1) << 3) + rr) * LDA_S + ((mi >> 1) << 2)) << 2);
    const uint32_t bAddr0 = bs_u32 +
        (((n_base + ((mi >> 1) << 3) + rr) * LDA_S + ((mi & 1) << 2)) << 2);

    float acc[FM][FN][4] = {};
    float facr[FM][2];
    if (FAC) {   // reciprocal of accumulated row sums; constant over k
        const float* fb = fac + (long)bz * M + row0 + m_base + grp;
#pragma unroll
        for (int i = 0; i < FM; i++) {
            facr[i][0] = 1.f / fb[i * 16];
            facr[i][1] = 1.f / fb[i * 16 + 8];
        }
    }

    auto issue = [&](int st, int k0) {
#pragma unroll
        for (int l = 0; l < NA; l++) {
            int i = tid + l * NTH;
            int r = i / KQ, kq = i % KQ;
            cp_async16(smem_u32 + st * A_STAGE_B + ((r * LDA_S + kq * 4) << 2),
                       A + (long)(row0 + r) * lda + k0 + kq * 4);
        }
#pragma unroll
        for (int l = 0; l < NB; l++) {
            int i = tid + l * NTH;
            if (!TRANS_B) {
                int kk = i / (BN / 4), nq = i % (BN / 4);
                cp_async16(bs_u32 + st * BN_STAGE_B + ((kk * LDB_S + nq * 4) << 2),
                           Bm + (long)(k0 + kk) * ldb + col0 + nq * 4);
            } else {
                int n = i / KQ, kq = i % KQ;
                cp_async16(bs_u32 + st * BT_STAGE_B + ((n * LDA_S + kq * 4) << 2),
                           Bm + (long)(col0 + n) * ldb + k0 + kq * 4);
            }
        }
    };

    const int kt = K / KBT;
#pragma unroll
    for (int s = 0; s < STAGES - 1; s++) {
        issue(s, s * KBT);
        asm volatile("cp.async.commit_group;\n");
    }

    for (int t = 0; t < kt; t++) {
        asm volatile("cp.async.wait_group %0;\n" :: "n"(STAGES - 2));
        __syncthreads();
        const int st = t % STAGES;
        const int nx = t + STAGES - 1;
        if (nx < kt) issue(nx % STAGES, nx * KBT);
        asm volatile("cp.async.commit_group;\n");

        const uint32_t aSt = aAddr0 + st * A_STAGE_B;
        const uint32_t bSt = bAddr0 + st * BT_STAGE_B;

#pragma unroll
        for (int kc = 0; kc < KBT / 8; kc++) {
            const int kk = kc * 8;
            uint32_t af[FM][4], bf[FN][2];
#pragma unroll
            for (int i = 0; i < FM; i++) {
                ldsm_x4(af[i], aSt + i * (16 * LDA_S * 4) + kc * 32);
                if (FAC) {
                    af[i][0] = f2tf32(__uint_as_float(af[i][0]) * facr[i][0]);
                    af[i][1] = f2tf32(__uint_as_float(af[i][1]) * facr[i][1]);
                    af[i][2] = f2tf32(__uint_as_float(af[i][2]) * facr[i][0]);
                    af[i][3] = f2tf32(__uint_as_float(af[i][3]) * facr[i][1]);
                } else if (CVT_A) {
#pragma unroll
                    for (int q = 0; q < 4; q++) af[i][q] = f2tf32(__uint_as_float(af[i][q]));
                }
            }
            if (TRANS_B) {
#pragma unroll
                for (int jp = 0; jp < FN / 2; jp++) {
                    uint32_t tmp4[4];
                    ldsm_x4(tmp4, bSt + jp * (16 * LDA_S * 4) + kc * 32);
                    if (CVT_B) {
#pragma unroll
                        for (int q = 0; q < 4; q++) tmp4[q] = f2tf32(__uint_as_float(tmp4[q]));
                    }
                    bf[jp * 2][0] = tmp4[0]; bf[jp * 2][1] = tmp4[1];
                    bf[jp * 2 + 1][0] = tmp4[2]; bf[jp * 2 + 1][1] = tmp4[3];
                }
            } else {
#pragma unroll
                for (int j = 0; j < FN; j++) {
                    int n = n_base + j * 8 + grp;
                    float b0 = Bs_[(st * KBT + kk + qid) * LDB_S + n];
                    float b1 = Bs_[(st * KBT + kk + qid + 4) * LDB_S + n];
                    bf[j][0] = CVT_B ? f2tf32(b0) : __float_as_uint(b0);
                    bf[j][1] = CVT_B ? f2tf32(b1) : __float_as_uint(b1);
                }
            }
#pragma unroll
            for (int i = 0; i < FM; i++)
#pragma unroll
                for (int j = 0; j < FN; j++) mma_tf32(acc[i][j], af[i], bf[j]);
        }
    }

    // ---- epilogue ----
    float rs[FM][2];
    if (SUMS) {
#pragma unroll
        for (int i = 0; i < FM; i++) { rs[i][0] = 0.f; rs[i][1] = 0.f; }
    }
#pragma unroll
    for (int i = 0; i < FM; i++) {
        int r0 = row0 + m_base + i * 16 + grp;
#pragma unroll
        for (int j = 0; j < FN; j++) {
            int c = col0 + n_base + j * 8 + qid * 2;
            float2 v0 = {acc[i][j][0] * alpha, acc[i][j][1] * alpha};
            float2 v1 = {acc[i][j][2] * alpha, acc[i][j][3] * alpha};
            if (EXPC) {
                v0.x = __expf(v0.x); v0.y = __expf(v0.y);
                v1.x = __expf(v1.x); v1.y = __expf(v1.y);
            }
            if (SUMS) {
                rs[i][0] += v0.x + v0.y;
                rs[i][1] += v1.x + v1.y;
            }
            if (RESID) {
                int rr0 = RMOD ? (r0 % RMOD) : r0;
                int rr1 = RMOD ? ((r0 + 8) % RMOD) : (r0 + 8);
                float2 r0v = *(const float2*)(R + (long)rr0 * ldr + c);
                float2 r1v = *(const float2*)(R + (long)rr1 * ldr + c);
                v0.x += beta * r0v.x; v0.y += beta * r0v.y;
                v1.x += beta * r1v.x; v1.y += beta * r1v.y;
            }
            if (RESID2) {
                float2 a0 = *(const float2*)(R2 + (long)(r0 % N_) * N_ + c);
                float2 a1 = *(const float2*)(R2 + (long)((r0 + 8) % N_) * N_ + c);
                v0.x += a0.x; v0.y += a0.y;
                v1.x += a1.x; v1.y += a1.y;
            }
            if (ROUND_C) {
                v0.x = roundtf(v0.x); v0.y = roundtf(v0.y);
                v1.x = roundtf(v1.x); v1.y = roundtf(v1.y);
            }
            *(float2*)(C + (long)r0 * ldc + c) = v0;
            *(float2*)(C + (long)(r0 + 8) * ldc + c) = v1;
        }
    }
    if (SUMS) {
#pragma unroll
        for (int i = 0; i < FM; i++)
#pragma unroll
            for (int h = 0; h < 2; h++) {
                float s = rs[i][h];
                s += __shfl_xor_sync(0xffffffffu, s, 1);
                s += __shfl_xor_sync(0xffffffffu, s, 2);
                if (qid == 0)
                    atomicAdd(fac + (long)bz * M + row0 + m_base + i * 16 + grp + h * 8, s);
            }
    }
}

// host-side smem size mirror (BK=32, 3 stages)
static inline int gemm_smem_bytes(int BM, int BN, bool transB) {
    const int STAGES = 3, KBT = 32, LDA_S = KBT + 4;
    int a = STAGES * BM * LDA_S;
    int b = transB ? STAGES * BN * LDA_S : STAGES * KBT * (BN + 8);
    return (a + b) * 4;
}

// ---------------- launch ----------------------------------------------------
extern "C" void kernel_launch(void* const* d_in, const int* in_sizes, int n_in,
                              void* d_out, int out_size) {
    const float* inputs = (const float*)d_in[0];
    const float* W_in  = (const float*)d_in[2];
    const float* T_mix = (const float*)d_in[3];
    const float* Wq    = (const float*)d_in[4];
    const float* Wk    = (const float*)d_in[5];
    const float* Wv    = (const float*)d_in[6];
    const float* W_out = (const float*)d_in[7];
    const float* A     = (const float*)d_in[8];

    float* out = (float*)d_out;
    float* mgt = out;
    float* kal = out + (long)B_ * Q_ * N_ * F_;

    float *tmp, *h, *qkv, *S, *CP, *WinT, *WqkvT, *WoutT, *WcombT, *fac;
    cudaGetSymbolAddress((void**)&tmp, g_tmp);
    cudaGetSymbolAddress((void**)&h, g_h);
    cudaGetSymbolAddress((void**)&qkv, g_qkv);
    cudaGetSymbolAddress((void**)&S, g_S);
    cudaGetSymbolAddress((void**)&CP, g_CP);
    cudaGetSymbolAddress((void**)&WinT, g_WinT);
    cudaGetSymbolAddress((void**)&WqkvT, g_WqkvT);
    cudaGetSymbolAddress((void**)&WoutT, g_WoutT);
    cudaGetSymbolAddress((void**)&WcombT, g_WcombT);
    cudaGetSymbolAddress((void**)&fac, g_fac);

    const long sNN = (long)N_ * N_;
    const long sNF = (long)N_ * F_;
    const long sQKV = (long)N_ * 3 * D_;
    const long sH = (long)N_ * D_;

    // GEMM instances: BN=128, warp tile 64x32, 2 CTAs/SM, BK=32
    auto kNT  = gemm_tc<128, 128, 2, 4, true,  false, 0,  false, false, true,  false, false, false, false, 32, 2>;
    auto kQK  = gemm_tc<128, 128, 2, 4, true,  false, 0,  false, false, false, false, true,  false, true,  32, 2>;
    auto kAV  = gemm_tc<128, 128, 2, 4, false, true,  0,  false, false, true,  false, false, true,  false, 32, 2>;
    auto kOUT = gemm_tc<128, 64,  2, 2, true,  false, 0,  false, false, false, false, false, false, false, 32, 2>;
    auto kWC  = gemm_tc<128, 64,  2, 2, false, false, 0,  false, false, true,  false, false, false, false, 32, 2>;
    auto kCP  = gemm_tc<128, 128, 2, 4, false, true,  0,  false, false, true,  true,  false, false, false, 32, 2>;
    auto kKAL = gemm_tc<128, 64,  2, 2, false, true,  N_, false, true,  false, false, false, false, false, 32, 2>;

    const int smNT   = gemm_smem_bytes(128, 128, true);
    const int smNN   = gemm_smem_bytes(128, 128, false);
    const int smNT64 = gemm_smem_bytes(128, 64, true);
    const int smNN64 = gemm_smem_bytes(128, 64, false);
    cudaFuncSetAttribute(kNT,  cudaFuncAttributeMaxDynamicSharedMemorySize, smNT);
    cudaFuncSetAttribute(kQK,  cudaFuncAttributeMaxDynamicSharedMemorySize, smNT);
    cudaFuncSetAttribute(kAV,  cudaFuncAttributeMaxDynamicSharedMemorySize, smNN);
    cudaFuncSetAttribute(kOUT, cudaFuncAttributeMaxDynamicSharedMemorySize, smNT64);
    cudaFuncSetAttribute(kWC,  cudaFuncAttributeMaxDynamicSharedMemorySize, smNN64);
    cudaFuncSetAttribute(kCP,  cudaFuncAttributeMaxDynamicSharedMemorySize, smNN);
    cudaFuncSetAttribute(kKAL, cudaFuncAttributeMaxDynamicSharedMemorySize, smNN64);

    // launch 0: fused setup (mix, weight prep, c1, fac=0)
    setup_kernel<<<((long)B_ * N_ * F_ + 255) / 256, 256>>>(
        inputs, T_mix, W_in, Wq, Wk, Wv, W_out, A);

    // launch 1 — W_combT = WqkvT @ WinT  (768x64x256, NN, tf32-rounded out)
    kWC<<<dim3(1, 3 * D_ / 128, 1), 128, smNN64>>>(
        WqkvT, WinT, WcombT, nullptr, nullptr, nullptr,
        3 * D_, F_, D_, D_, F_, F_, 0, 0, 0, 0, 0, 1.f, 0.f);

    // launch 2 — K2: h = tmp @ WinT^T   (needed for K6 residual)
    kNT<<<dim3(2, BQN / 128, 1), 256, smNT>>>(
        tmp, WinT, h, nullptr, nullptr, nullptr,
        BQN, D_, F_, F_, F_, D_, 0, 0, 0, 0, 0, 1.f, 0.f);

    // launch 3 — K3': qkv = tmp @ W_combT^T   (K=64: 4x fewer flops than h@Wqkv)
    kNT<<<dim3(6, BQN / 128, 1), 256, smNT>>>(
        tmp, WcombT, qkv, nullptr, nullptr, nullptr,
        BQN, 3 * D_, F_, F_, F_, 3 * D_, 0, 0, 0, 0, 0, 1.f, 0.f);

    // launch 4 — K4: S = exp(q @ k^T), row sums accumulated into fac
    kQK<<<dim3(4, 4, NBQ), 256, smNT>>>(
        qkv, qkv + D_, S, nullptr, nullptr, fac,
        N_, N_, D_, 3 * D_, 3 * D_, N_, 0, sQKV, sQKV, sNN, 0, 1.f, 0.f);

    // launch 5 — K6: h = h + (S / rowsum) @ v
    kAV<<<dim3(2, 4, NBQ), 256, smNN>>>(
        S, qkv + 2 * D_, h, h, nullptr, fac,
        N_, D_, N_, N_, 3 * D_, D_, D_, sNN, sQKV, sH, sH, 1.f, 1.f);

    // launch 6 — K7: mgt = h @ WoutT^T
    kOUT<<<dim3(1, BQN / 128, 1), 128, smNT64>>>(
        h, WoutT, mgt, nullptr, nullptr, nullptr,
        BQN, F_, D_, D_, D_, F_, 0, 0, 0, 0, 0, 1.f, 0.f);

    // CP chain (independent; feeds only the final Kalman GEMM)
    float* c1 = CP;
    float* c2 = CP + sNN;
    float* c4 = CP + 3 * sNN;
    float* c8 = CP + 7 * sNN;
    kCP<<<dim3(4, 4, 1), 256, smNN>>>(c1, c1, c2, c1, c1, nullptr,
        N_, N_, N_, N_, N_, N_, N_, 0, 0, 0, 0, 1.f, 1.f);
    kCP<<<dim3(4, 8, 1), 256, smNN>>>(CP, c2, CP + 2 * sNN, CP, c2, nullptr,
        2 * N_, N_, N_, N_, N_, N_, N_, 0, 0, 0, 0, 1.f, 1.f);
    kCP<<<dim3(4, 16, 1), 256, smNN>>>(CP, c4, CP + 4 * sNN, CP, c4, nullptr,
        4 * N_, N_, N_, N_, N_, N_, N_, 0, 0, 0, 0, 1.f, 1.f);
    kCP<<<dim3(4, 16, 1), 256, smNN>>>(CP, c8, CP + 8 * sNN, CP, c8, nullptr,
        4 * N_, N_, N_, N_, N_, N_, N_, 0, 0, 0, 0, 1.f, 1.f);

    // Kalman (single parallel launch): kal[b, t] = c_{t+1} @ mu0[b] + mu0[b]
    const float* mu0 = inputs + (long)(P_ - 1) * sNF;
    kKAL<<<dim3(1, 12 * N_ / 128, B_), 128, smNN64>>>(
        CP, mu0, kal, mu0, nullptr, nullptr,
        12 * N_, F_, N_, N_, F_, F_, F_,
        0, (long)P_ * sNF, (long)Q_ * sNF, (long)P_ * sNF, 1.f, 1.f);
}

// round 14
// speedup vs baseline: 1.5855x; 1.2399x over previous
#include <cuda_runtime.h>
#include <cuda_fp16.h>
#include <cstdint>

// Problem dims
#define B_ 32
#define P_ 12
#define N_ 512
#define F_ 64
#define D_ 256
#define Q_ 12
#define DT_ 0.1f

static const int BQN = B_ * Q_ * N_;  // 196608
#define NBQ (B_ * Q_)                 // 384
#define EXPSHIFT 8.0f                 // softmax shift (cancels in normalization)

// ---------------- scratch (device globals; no runtime alloc) ----------------
__device__ float  g_tmp  [(size_t)B_ * Q_ * N_ * F_];    // mixed inputs (tf32 bits)
__device__ float  g_h    [(size_t)B_ * Q_ * N_ * D_];    // hidden (tf32 bits)
__device__ __half g_qk   [(size_t)B_ * Q_ * N_ * 2 * D_];// q|k fp16, ld=512
__device__ __half g_vT   [(size_t)NBQ * D_ * N_];        // v transposed fp16 [d][n]
__device__ __half g_S    [(size_t)B_ * Q_ * N_ * N_];    // exp'd scores fp16
__device__ float  g_CP   [(size_t)12 * N_ * N_];         // c_k = (I+DT*A)^k - I, tf32
__device__ float  g_WinT [(size_t)D_ * F_];              // W_in^T  (256x64)  tf32
__device__ float  g_WqkvT[(size_t)3 * D_ * D_];          // Wqkv^T  (768x256) tf32
__device__ float  g_WoutT[(size_t)F_ * D_];              // W_out^T (64x256)  tf32
__device__ float  g_WcombT[(size_t)3 * D_ * F_];         // (W_in@Wqkv)^T (768x64)
__device__ float  g_fac  [(size_t)NBQ * N_];             // rowsum(exp), atomic

// ---------------- helpers ----------------------------------------------------
__device__ __forceinline__ uint32_t f2tf32(float f) {
    uint32_t u;
    asm("cvt.rna.tf32.f32 %0, %1;" : "=r"(u) : "f"(f));
    return u;
}
__device__ __forceinline__ float roundtf(float f) { return __uint_as_float(f2tf32(f)); }

__device__ __forceinline__ void mma_tf32(float* c, const uint32_t* a, const uint32_t* b) {
    asm volatile(
        "mma.sync.aligned.m16n8k8.row.col.f32.tf32.tf32.f32 "
        "{%0,%1,%2,%3}, {%4,%5,%6,%7}, {%8,%9}, {%0,%1,%2,%3};"
        : "+f"(c[0]), "+f"(c[1]), "+f"(c[2]), "+f"(c[3])
        : "r"(a[0]), "r"(a[1]), "r"(a[2]), "r"(a[3]),
          "r"(b[0]), "r"(b[1]));
}

__device__ __forceinline__ void mma_f16(float* c, const uint32_t* a, const uint32_t* b) {
    asm volatile(
        "mma.sync.aligned.m16n8k16.row.col.f32.f16.f16.f32 "
        "{%0,%1,%2,%3}, {%4,%5,%6,%7}, {%8,%9}, {%0,%1,%2,%3};"
        : "+f"(c[0]), "+f"(c[1]), "+f"(c[2]), "+f"(c[3])
        : "r"(a[0]), "r"(a[1]), "r"(a[2]), "r"(a[3]),
          "r"(b[0]), "r"(b[1]));
}

__device__ __forceinline__ void ldsm_x4(uint32_t* r, uint32_t addr) {
    asm volatile("ldmatrix.sync.aligned.m8n8.x4.shared.b16 {%0,%1,%2,%3}, [%4];"
                 : "=r"(r[0]), "=r"(r[1]), "=r"(r[2]), "=r"(r[3]) : "r"(addr));
}

__device__ __forceinline__ void cp_async16(uint32_t smem_dst, const void* gsrc) {
    asm volatile("cp.async.cg.shared.global [%0], [%1], 16;\n" :: "r"(smem_dst), "l"(gsrc));
}

// ---------------- K0: fused setup --------------------------------------------
__global__ __launch_bounds__(256) void setup_kernel(const float* __restrict__ in,
                                                    const float* __restrict__ T,
                                                    const float* __restrict__ Win,
                                                    const float* __restrict__ Wq,
                                                    const float* __restrict__ Wk,
                                                    const float* __restrict__ Wv,
                                                    const float* __restrict__ Wout,
                                                    const float* __restrict__ A) {
    __shared__ float Ts[P_][Q_];
    int t = threadIdx.x;
    if (t < P_ * Q_) Ts[t / Q_][t % Q_] = T[t];
    long idx = (long)blockIdx.x * 256 + t;

    if (idx < (long)D_ * D_) {
        int r = (int)(idx / D_), c = (int)(idx % D_);
        g_WqkvT[(long)c * D_ + r]            = roundtf(Wq[idx] * 0.0625f);
        g_WqkvT[(long)(D_ + c) * D_ + r]     = roundtf(Wk[idx]);
        g_WqkvT[(long)(2 * D_ + c) * D_ + r] = roundtf(Wv[idx]);
    }
    if (idx < (long)F_ * D_) {
        int r = (int)(idx / D_), c = (int)(idx % D_);
        g_WinT[(long)c * F_ + r] = roundtf(Win[idx]);
    }
    if (idx < (long)D_ * F_) {
        int r = (int)(idx / F_), c = (int)(idx % F_);
        g_WoutT[(long)c * D_ + r] = roundtf(Wout[idx]);
    }
    if (idx < (long)N_ * N_) g_CP[idx] = roundtf(DT_ * A[idx]);
    if (idx < (long)NBQ * N_) g_fac[idx] = 0.f;

    __syncthreads();
    if (idx < (long)B_ * N_ * F_) {
        int f = (int)(idx % F_);
        int n = (int)((idx / F_) % N_);
        int b = (int)(idx / ((long)F_ * N_));
        float vals[P_];
        const float* ip = in + ((long)b * P_ * N_ + n) * F_ + f;
#pragma unroll
        for (int p = 0; p < P_; p++) vals[p] = ip[(long)p * N_ * F_];
        float* op = g_tmp + ((long)b * Q_ * N_ + n) * F_ + f;
#pragma unroll
        for (int q = 0; q < Q_; q++) {
            float s = 0.f;
#pragma unroll
            for (int p = 0; p < P_; p++) s += vals[p] * Ts[p][q];
            op[(long)q * N_ * F_] = roundtf(s);
        }
    }
}

// ---------------- tf32 GEMM (cp.async x3 + ldmatrix, BK=32) ------------------
// C = alpha*A*op(B) + beta*R (RESID) + R2[row%512] (RESID2).
// HALF_C: C is __half buffer (ldc in halves). RMOD>0: residual row = row%RMOD.
template <int BM, int BN, int WM, int WN, bool TRANS_B, bool RESID, int RMOD,
          bool CVT_B, bool ROUND_C, bool RESID2, bool HALF_C, int OCC>
__global__ __launch_bounds__(WM* WN * 32, OCC) void gemm_tc(
    const float* __restrict__ A, const float* __restrict__ Bm,
    void* __restrict__ Cv, const float* __restrict__ R,
    const float* __restrict__ R2,
    int M, int Nn, int K, int lda, int ldb, int ldc, int ldr,
    long sA, long sB, long sC, long sR, float alpha, float beta) {
    constexpr int KBT = 32;
    constexpr int STAGES = 3;
    constexpr int NTH = WM * WN * 32;
    constexpr int WTM = BM / WM, WTN = BN / WN;
    constexpr int FM = WTM / 16, FN = WTN / 8;
    constexpr int KQ = KBT / 4;
    constexpr int LDA_S = KBT + 4;         // 36 words
    constexpr int LDB_S = BN + 8;
    constexpr int NA = BM * KBT / (4 * NTH);
    constexpr int NB = BN * KBT / (4 * NTH);
    constexpr int A_STAGE_B = BM * LDA_S * 4;
    constexpr int BT_STAGE_B = BN * LDA_S * 4;
    constexpr int BN_STAGE_B = KBT * LDB_S * 4;

    extern __shared__ __align__(16) float smem[];
    float* Bs_ = smem + STAGES * BM * LDA_S;
    const uint32_t smem_u32 = (uint32_t)__cvta_generic_to_shared(smem);
    const uint32_t bs_u32 = smem_u32 + STAGES * A_STAGE_B;

    const int bz = blockIdx.z;
    A += (long)bz * sA;
    Bm += (long)bz * sB;
    if (RESID) R += (long)bz * sR;

    const int row0 = blockIdx.y * BM, col0 = blockIdx.x * BN;
    const int tid = threadIdx.x;
    const int lane = tid & 31, wid = tid >> 5;
    const int grp = lane >> 2, qid = lane & 3;
    const int wm = wid / WN, wn = wid % WN;
    const int m_base = wm * WTM, n_base = wn * WTN;

    const int mi = lane >> 3, rr = lane & 7;
    const uint32_t aAddr0 = smem_u32 +
        (((m_base + ((mi & 1) << 3) + rr) * LDA_S + ((mi >> 1) << 2)) << 2);
    const uint32_t bAddr0 = bs_u32 +
        (((n_base + ((mi >> 1) << 3) + rr) * LDA_S + ((mi & 1) << 2)) << 2);

    float acc[FM][FN][4] = {};

    auto issue = [&](int st, int k0) {
#pragma unroll
        for (int l = 0; l < NA; l++) {
            int i = tid + l * NTH;
            int r = i / KQ, kq = i % KQ;
            cp_async16(smem_u32 + st * A_STAGE_B + ((r * LDA_S + kq * 4) << 2),
                       A + (long)(row0 + r) * lda + k0 + kq * 4);
        }
#pragma unroll
        for (int l = 0; l < NB; l++) {
            int i = tid + l * NTH;
            if (!TRANS_B) {
                int kk = i / (BN / 4), nq = i % (BN / 4);
                cp_async16(bs_u32 + st * BN_STAGE_B + ((kk * LDB_S + nq * 4) << 2),
                           Bm + (long)(k0 + kk) * ldb + col0 + nq * 4);
            } else {
                int n = i / KQ, kq = i % KQ;
                cp_async16(bs_u32 + st * BT_STAGE_B + ((n * LDA_S + kq * 4) << 2),
                           Bm + (long)(col0 + n) * ldb + k0 + kq * 4);
            }
        }
    };

    const int kt = K / KBT;
#pragma unroll
    for (int s = 0; s < STAGES - 1; s++) {
        issue(s, s * KBT);
        asm volatile("cp.async.commit_group;\n");
    }

    for (int t = 0; t < kt; t++) {
        asm volatile("cp.async.wait_group %0;\n" :: "n"(STAGES - 2));
        __syncthreads();
        const int st = t % STAGES;
        const int nx = t + STAGES - 1;
        if (nx < kt) issue(nx % STAGES, nx * KBT);
        asm volatile("cp.async.commit_group;\n");

        const uint32_t aSt = aAddr0 + st * A_STAGE_B;
        const uint32_t bSt = bAddr0 + st * BT_STAGE_B;

#pragma unroll
        for (int kc = 0; kc < KBT / 8; kc++) {
            const int kk = kc * 8;
            uint32_t af[FM][4], bf[FN][2];
#pragma unroll
            for (int i = 0; i < FM; i++)
                ldsm_x4(af[i], aSt + i * (16 * LDA_S * 4) + kc * 32);
            if (TRANS_B) {
#pragma unroll
                for (int jp = 0; jp < FN / 2; jp++) {
                    uint32_t tmp4[4];
                    ldsm_x4(tmp4, bSt + jp * (16 * LDA_S * 4) + kc * 32);
                    if (CVT_B) {
#pragma unroll
                        for (int q = 0; q < 4; q++) tmp4[q] = f2tf32(__uint_as_float(tmp4[q]));
                    }
                    bf[jp * 2][0] = tmp4[0]; bf[jp * 2][1] = tmp4[1];
                    bf[jp * 2 + 1][0] = tmp4[2]; bf[jp * 2 + 1][1] = tmp4[3];
                }
            } else {
#pragma unroll
                for (int j = 0; j < FN; j++) {
                    int n = n_base + j * 8 + grp;
                    float b0 = Bs_[(st * KBT + kk + qid) * LDB_S + n];
                    float b1 = Bs_[(st * KBT + kk + qid + 4) * LDB_S + n];
                    bf[j][0] = CVT_B ? f2tf32(b0) : __float_as_uint(b0);
                    bf[j][1] = CVT_B ? f2tf32(b1) : __float_as_uint(b1);
                }
            }
#pragma unroll
            for (int i = 0; i < FM; i++)
#pragma unroll
                for (int j = 0; j < FN; j++) mma_tf32(acc[i][j], af[i], bf[j]);
        }
    }

    float* C = (float*)Cv + (HALF_C ? 0 : (long)bz * sC);
    __half* Ch = (__half*)Cv + (HALF_C ? (long)bz * sC : 0);
#pragma unroll
    for (int i = 0; i < FM; i++) {
        int r0 = row0 + m_base + i * 16 + grp;
#pragma unroll
        for (int j = 0; j < FN; j++) {
            int c = col0 + n_base + j * 8 + qid * 2;
            float2 v0 = {acc[i][j][0] * alpha, acc[i][j][1] * alpha};
            float2 v1 = {acc[i][j][2] * alpha, acc[i][j][3] * alpha};
            if (RESID) {
                int rr0 = RMOD ? (r0 % RMOD) : r0;
                int rr1 = RMOD ? ((r0 + 8) % RMOD) : (r0 + 8);
                float2 r0v = *(const float2*)(R + (long)rr0 * ldr + c);
                float2 r1v = *(const float2*)(R + (long)rr1 * ldr + c);
                v0.x += beta * r0v.x; v0.y += beta * r0v.y;
                v1.x += beta * r1v.x; v1.y += beta * r1v.y;
            }
            if (RESID2) {
                float2 a0 = *(const float2*)(R2 + (long)(r0 % N_) * N_ + c);
                float2 a1 = *(const float2*)(R2 + (long)((r0 + 8) % N_) * N_ + c);
                v0.x += a0.x; v0.y += a0.y;
                v1.x += a1.x; v1.y += a1.y;
            }
            if (HALF_C) {
                *(__half2*)(Ch + (long)r0 * ldc + c) = __floats2half2_rn(v0.x, v0.y);
                *(__half2*)(Ch + (long)(r0 + 8) * ldc + c) = __floats2half2_rn(v1.x, v1.y);
            } else {
                if (ROUND_C) {
                    v0.x = roundtf(v0.x); v0.y = roundtf(v0.y);
                    v1.x = roundtf(v1.x); v1.y = roundtf(v1.y);
                }
                *(float2*)(C + (long)r0 * ldc + c) = v0;
                *(float2*)(C + (long)(r0 + 8) * ldc + c) = v1;
            }
        }
    }
}

// ---------------- fp16 NT GEMM (m16n8k16, cp.async x3 + ldmatrix) ------------
// A: M x K fp16 (lda, halves). B: Nn x K fp16 (ldb). C = A*B^T.
// EXPC: out = exp(acc - EXPSHIFT), stored fp16; SUMS: row sums -> atomicAdd fac.
// FACE: out rows scaled by 1/fac[bz*M+row]; RESID: + R fp32; out fp32 tf32-rounded.
template <int BM, int BN, bool EXPC, bool SUMS, bool FACE, bool RESID, int OCC>
__global__ __launch_bounds__(256, OCC) void gemm_f16(
    const __half* __restrict__ A, const __half* __restrict__ Bm,
    void* __restrict__ Cv, const float* __restrict__ R, float* __restrict__ fac,
    int M, int Nn, int K, int lda, int ldb, int ldc, int ldr,
    long sA, long sB, long sC, long sR) {
    constexpr int KBT = 32;                 // halves per k-tile
    constexpr int STAGES = 3;
    constexpr int NTH = 256;
    constexpr int WN = 4;
    constexpr int WTM = BM / 2, WTN = BN / WN;   // 64 x 32
    constexpr int FM = WTM / 16, FN = WTN / 8;   // 4 x 4
    constexpr int LDH = KBT + 8;            // 40 halves = 20 words: conflict-free
    constexpr int KQ = KBT / 8;             // 16B chunks per row (4)
    constexpr int NA = BM * KBT / (8 * NTH);
    constexpr int NB = BN * KBT / (8 * NTH);
    constexpr int A_STAGE_B = BM * LDH * 2;
    constexpr int B_STAGE_B = BN * LDH * 2;

    extern __shared__ __align__(16) __half hsm[];
    const uint32_t smem_u32 = (uint32_t)__cvta_generic_to_shared(hsm);
    const uint32_t bs_u32 = smem_u32 + STAGES * A_STAGE_B;

    const int bz = blockIdx.z;
    A += (long)bz * sA;
    Bm += (long)bz * sB;
    if (RESID) R += (long)bz * sR;

    const int row0 = blockIdx.y * BM, col0 = blockIdx.x * BN;
    const int tid = threadIdx.x;
    const int lane = tid & 31, wid = tid >> 5;
    const int grp = lane >> 2, qid = lane & 3;
    const int wm = wid / WN, wn = wid % WN;
    const int m_base = wm * WTM, n_base = wn * WTN;

    const int l16 = lane & 15, lh = lane >> 4;
    const uint32_t aAddr0 = smem_u32 + (((m_base + l16) * LDH + lh * 8) << 1);
    const uint32_t bAddr0 = bs_u32 + (((n_base + l16) * LDH + lh * 8) << 1);

    float acc[FM][FN][4] = {};

    auto issue = [&](int st, int k0) {
#pragma unroll
        for (int l = 0; l < NA; l++) {
            int i = tid + l * NTH;
            int r = i / KQ, kq = i % KQ;
            cp_async16(smem_u32 + st * A_STAGE_B + ((r * LDH + kq * 8) << 1),
                       A + (long)(row0 + r) * lda + k0 + kq * 8);
        }
#pragma unroll
        for (int l = 0; l < NB; l++) {
            int i = tid + l * NTH;
            int n = i / KQ, kq = i % KQ;
            cp_async16(bs_u32 + st * B_STAGE_B + ((n * LDH + kq * 8) << 1),
                       Bm + (long)(col0 + n) * ldb + k0 + kq * 8);
        }
    };

    const int kt = K / KBT;
#pragma unroll
    for (int s = 0; s < STAGES - 1; s++) {
        issue(s, s * KBT);
        asm volatile("cp.async.commit_group;\n");
    }

    for (int t = 0; t < kt; t++) {
        asm volatile("cp.async.wait_group %0;\n" :: "n"(STAGES - 2));
        __syncthreads();
        const int st = t % STAGES;
        const int nx = t + STAGES - 1;
        if (nx < kt) issue(nx % STAGES, nx * KBT);
        asm volatile("cp.async.commit_group;\n");

        const uint32_t aSt = aAddr0 + st * A_STAGE_B;
        const uint32_t bSt = bAddr0 + st * B_STAGE_B;

#pragma unroll
        for (int kc = 0; kc < 2; kc++) {       // two k16 chunks
            uint32_t af[FM][4], bf[FN][2];
#pragma unroll
            for (int i = 0; i < FM; i++)
                ldsm_x4(af[i], aSt + i * (16 * LDH * 2) + kc * 32);
#pragma unroll
            for (int jp = 0; jp < FN / 2; jp++) {
                uint32_t t4[4];
                ldsm_x4(t4, bSt + jp * (16 * LDH * 2) + kc * 32);
                bf[jp * 2][0] = t4[0];     bf[jp * 2][1] = t4[2];
                bf[jp * 2 + 1][0] = t4[1]; bf[jp * 2 + 1][1] = t4[3];
            }
#pragma unroll
            for (int i = 0; i < FM; i++)
#pragma unroll
                for (int j = 0; j < FN; j++) mma_f16(acc[i][j], af[i], bf[j]);
        }
    }

    __half* Ch = (__half*)Cv + (EXPC ? (long)bz * sC : 0);
    float* Cf = (float*)Cv + (EXPC ? 0 : (long)bz * sC);
    float facr[FM][2];
    if (FACE) {
        const float* fb = fac + (long)bz * M + row0 + m_base + grp;
#pragma unroll
        for (int i = 0; i < FM; i++) {
            facr[i][0] = 1.f / fb[i * 16];
            facr[i][1] = 1.f / fb[i * 16 + 8];
        }
    }
    float rs[FM][2];
    if (SUMS) {
#pragma unroll
        for (int i = 0; i < FM; i++) { rs[i][0] = 0.f; rs[i][1] = 0.f; }
    }
#pragma unroll
    for (int i = 0; i < FM; i++) {
        int r0 = row0 + m_base + i * 16 + grp;
#pragma unroll
        for (int j = 0; j < FN; j++) {
            int c = col0 + n_base + j * 8 + qid * 2;
            if (EXPC) {
                __half h00 = __float2half_rn(__expf(acc[i][j][0] - EXPSHIFT));
                __half h01 = __float2half_rn(__expf(acc[i][j][1] - EXPSHIFT));
                __half h10 = __float2half_rn(__expf(acc[i][j][2] - EXPSHIFT));
                __half h11 = __float2half_rn(__expf(acc[i][j][3] - EXPSHIFT));
                if (SUMS) {   // sum post-rounding values: denominator matches stored S
                    rs[i][0] += __half2float(h00) + __half2float(h01);
                    rs[i][1] += __half2float(h10) + __half2float(h11);
                }
                *(__half2*)(Ch + (long)r0 * ldc + c) = __halves2half2(h00, h01);
                *(__half2*)(Ch + (long)(r0 + 8) * ldc + c) = __halves2half2(h10, h11);
            } else {
                float2 v0 = {acc[i][j][0], acc[i][j][1]};
                float2 v1 = {acc[i][j][2], acc[i][j][3]};
                if (FACE) {
                    v0.x *= facr[i][0]; v0.y *= facr[i][0];
                    v1.x *= facr[i][1]; v1.y *= facr[i][1];
                }
                if (RESID) {
                    float2 r0v = *(const float2*)(R + (long)r0 * ldr + c);
                    float2 r1v = *(const float2*)(R + (long)(r0 + 8) * ldr + c);
                    v0.x += r0v.x; v0.y += r0v.y;
                    v1.x += r1v.x; v1.y += r1v.y;
                }
                v0.x = roundtf(v0.x); v0.y = roundtf(v0.y);
                v1.x = roundtf(v1.x); v1.y = roundtf(v1.y);
                *(float2*)(Cf + (long)r0 * ldc + c) = v0;
                *(float2*)(Cf + (long)(r0 + 8) * ldc + c) = v1;
            }
        }
    }
    if (SUMS) {
#pragma unroll
        for (int i = 0; i < FM; i++)
#pragma unroll
            for (int h = 0; h < 2; h++) {
                float s = rs[i][h];
                s += __shfl_xor_sync(0xffffffffu, s, 1);
                s += __shfl_xor_sync(0xffffffffu, s, 2);
                if (qid == 0)
                    atomicAdd(fac + (long)bz * M + row0 + m_base + i * 16 + grp + h * 8, s);
            }
    }
}

// host-side smem mirrors
static inline int gemm_smem_bytes(int BM, int BN, bool transB) {
    const int STAGES = 3, KBT = 32, LDA_S = KBT + 4;
    int a = STAGES * BM * LDA_S;
    int b = transB ? STAGES * BN * LDA_S : STAGES * KBT * (BN + 8);
    return (a + b) * 4;
}
static inline int gemm_f16_smem_bytes(int BM, int BN) {
    const int STAGES = 3, LDH = 40;
    return STAGES * (BM + BN) * LDH * 2;
}

// ---------------- launch ----------------------------------------------------
extern "C" void kernel_launch(void* const* d_in, const int* in_sizes, int n_in,
                              void* d_out, int out_size) {
    const float* inputs = (const float*)d_in[0];
    const float* W_in  = (const float*)d_in[2];
    const float* T_mix = (const float*)d_in[3];
    const float* Wq    = (const float*)d_in[4];
    const float* Wk    = (const float*)d_in[5];
    const float* Wv    = (const float*)d_in[6];
    const float* W_out = (const float*)d_in[7];
    const float* A     = (const float*)d_in[8];

    float* out = (float*)d_out;
    float* mgt = out;
    float* kal = out + (long)B_ * Q_ * N_ * F_;

    float *tmp, *h, *CP, *WinT, *WqkvT, *WoutT, *WcombT, *fac;
    __half *qk, *vT, *S;
    cudaGetSymbolAddress((void**)&tmp, g_tmp);
    cudaGetSymbolAddress((void**)&h, g_h);
    cudaGetSymbolAddress((void**)&qk, g_qk);
    cudaGetSymbolAddress((void**)&vT, g_vT);
    cudaGetSymbolAddress((void**)&S, g_S);
    cudaGetSymbolAddress((void**)&CP, g_CP);
    cudaGetSymbolAddress((void**)&WinT, g_WinT);
    cudaGetSymbolAddress((void**)&WqkvT, g_WqkvT);
    cudaGetSymbolAddress((void**)&WoutT, g_WoutT);
    cudaGetSymbolAddress((void**)&WcombT, g_WcombT);
    cudaGetSymbolAddress((void**)&fac, g_fac);

    const long sNN = (long)N_ * N_;
    const long sNF = (long)N_ * F_;
    const long sQK = (long)N_ * 2 * D_;   // per-(b,q) stride in qk (halves)
    const long sVT = (long)D_ * N_;       // per-(b,q) stride in vT (halves)
    const long sH = (long)N_ * D_;

    // tf32 instances
    auto kNT   = gemm_tc<128, 128, 2, 4, true,  false, 0,  false, true,  false, false, 2>;  // K2
    auto kQKP  = gemm_tc<128, 128, 2, 4, true,  false, 0,  false, false, false, true,  2>;  // K3qk->fp16
    auto kVT   = gemm_tc<128, 128, 2, 4, true,  false, 0,  false, false, false, true,  2>;  // vT->fp16
    auto kOUT  = gemm_tc<128, 64,  2, 2, true,  false, 0,  false, false, false, false, 2>;  // K7
    auto kWC   = gemm_tc<128, 64,  2, 2, false, false, 0,  false, true,  false, false, 2>;  // Wcomb
    auto kCP   = gemm_tc<128, 128, 2, 4, false, true,  0,  false, true,  true,  false, 2>;  // CP chain (+R +R2!)
    auto kKAL  = gemm_tc<128, 64,  2, 2, false, true,  N_, true,  false, false, false, 2>;  // Kalman
    // fp16 instances
    auto kQK16 = gemm_f16<128, 128, true,  true,  false, false, 2>;   // K4
    auto kAV16 = gemm_f16<128, 128, false, false, true,  true,  2>;   // K6

    const int smNT   = gemm_smem_bytes(128, 128, true);
    const int smNN   = gemm_smem_bytes(128, 128, false);
    const int smNT64 = gemm_smem_bytes(128, 64, true);
    const int smNN64 = gemm_smem_bytes(128, 64, false);
    const int smF16  = gemm_f16_smem_bytes(128, 128);
    cudaFuncSetAttribute(kNT,   cudaFuncAttributeMaxDynamicSharedMemorySize, smNT);
    cudaFuncSetAttribute(kQKP,  cudaFuncAttributeMaxDynamicSharedMemorySize, smNT);
    cudaFuncSetAttribute(kOUT,  cudaFuncAttributeMaxDynamicSharedMemorySize, smNT64);
    cudaFuncSetAttribute(kWC,   cudaFuncAttributeMaxDynamicSharedMemorySize, smNN64);
    cudaFuncSetAttribute(kCP,   cudaFuncAttributeMaxDynamicSharedMemorySize, smNN);
    cudaFuncSetAttribute(kKAL,  cudaFuncAttributeMaxDynamicSharedMemorySize, smNN64);
    cudaFuncSetAttribute(kQK16, cudaFuncAttributeMaxDynamicSharedMemorySize, smF16);
    cudaFuncSetAttribute(kAV16, cudaFuncAttributeMaxDynamicSharedMemorySize, smF16);

    // launch 0: fused setup
    setup_kernel<<<((long)B_ * N_ * F_ + 255) / 256, 256>>>(
        inputs, T_mix, W_in, Wq, Wk, Wv, W_out, A);

    // launch 1 — W_combT = WqkvT @ WinT (768x64x256, NN)
    kWC<<<dim3(1, 3 * D_ / 128, 1), 128, smNN64>>>(
        WqkvT, WinT, WcombT, nullptr, nullptr,
        3 * D_, F_, D_, D_, F_, F_, 0, 0, 0, 0, 0, 1.f, 0.f);

    // launch 2 — qk = tmp @ Wcomb_qk^T (K=64, fp16 out, ld=512)
    kQKP<<<dim3(4, BQN / 128, 1), 256, smNT>>>(
        tmp, WcombT, qk, nullptr, nullptr,
        BQN, 2 * D_, F_, F_, F_, 2 * D_, 0, 0, 0, 0, 0, 1.f, 0.f);

    // launch 3 — K4: S = exp(q@k^T - 8) fp16, rowsums -> fac  (profiled)
    kQK16<<<dim3(4, 4, NBQ), 256, smF16>>>(
        qk, qk + D_, S, nullptr, fac,
        N_, N_, D_, 2 * D_, 2 * D_, N_, 0, sQK, sQK, sNN, 0);

    // launch 4 — K2: h = tmp @ WinT^T (fp32, for K6 residual)
    kNT<<<dim3(2, BQN / 128, 1), 256, smNT>>>(
        tmp, WinT, h, nullptr, nullptr,
        BQN, D_, F_, F_, F_, D_, 0, 0, 0, 0, 0, 1.f, 0.f);

    // launch 5 — vT[bq] = Wcomb_v @ tmp[bq]^T (256x512x64 NT, fp16 out)
    kVT<<<dim3(4, 2, NBQ), 256, smNT>>>(
        WcombT + (long)2 * D_ * F_, tmp, vT, nullptr, nullptr,
        D_, N_, F_, F_, F_, N_, 0, 0, (long)N_ * F_, sVT, 0, 1.f, 0.f);

    // launch 6 — K6: h = h + (S @ vT^T) * (1/rowsum)   (fp16 NT, fp32 out)
    kAV16<<<dim3(2, 4, NBQ), 256, smF16>>>(
        S, vT, h, h, fac,
        N_, D_, N_, N_, N_, D_, D_, sNN, sVT, sH, sH);

    // launch 7 — K7: mgt = h @ WoutT^T
    kOUT<<<dim3(1, BQN / 128, 1), 128, smNT64>>>(
        h, WoutT, mgt, nullptr, nullptr,
        BQN, F_, D_, D_, D_, F_, 0, 0, 0, 0, 0, 1.f, 0.f);

    // CP chain: c_{k+j} = c_k @ c_j + c_k (RESID) + c_j (RESID2 broadcast)
    float* c1 = CP;
    float* c2 = CP + sNN;
    float* c4 = CP + 3 * sNN;
    float* c8 = CP + 7 * sNN;
    kCP<<<dim3(4, 4, 1), 256, smNN>>>(c1, c1, c2, c1, c1,
        N_, N_, N_, N_, N_, N_, N_, 0, 0, 0, 0, 1.f, 1.f);
    kCP<<<dim3(4, 8, 1), 256, smNN>>>(CP, c2, CP + 2 * sNN, CP, c2,
        2 * N_, N_, N_, N_, N_, N_, N_, 0, 0, 0, 0, 1.f, 1.f);
    kCP<<<dim3(4, 16, 1), 256, smNN>>>(CP, c4, CP + 4 * sNN, CP, c4,
        4 * N_, N_, N_, N_, N_, N_, N_, 0, 0, 0, 0, 1.f, 1.f);
    kCP<<<dim3(4, 16, 1), 256, smNN>>>(CP, c8, CP + 8 * sNN, CP, c8,
        4 * N_, N_, N_, N_, N_, N_, N_, 0, 0, 0, 0, 1.f, 1.f);

    // Kalman: kal[b, t] = c_{t+1} @ mu0[b] + mu0[b]  (one parallel launch)
    const float* mu0 = inputs + (long)(P_ - 1) * sNF;
    kKAL<<<dim3(1, 12 * N_ / 128, B_), 128, smNN64>>>(
        CP, mu0, kal, mu0, nullptr,
        12 * N_, F_, N_, N_, F_, F_, F_,
        0, (long)P_ * sNF, (long)Q_ * sNF, (long)P_ * sNF, 1.f, 1.f);
}

// round 15
// speedup vs baseline: 1.7558x; 1.1074x over previous
#include <cuda_runtime.h>
#include <cuda_fp16.h>
#include <cstdint>

// Problem dims
#define B_ 32
#define P_ 12
#define N_ 512
#define F_ 64
#define D_ 256
#define Q_ 12
#define DT_ 0.1f

static const int BQN = B_ * Q_ * N_;  // 196608
#define NBQ (B_ * Q_)                 // 384
#define EXPSHIFT 8.0f                 // softmax shift (cancels in normalization)

// ---------------- scratch (device globals; no runtime alloc) ----------------
__device__ float  g_tmp  [(size_t)B_ * Q_ * N_ * F_];    // mixed inputs (tf32 bits)
__device__ __half g_qk   [(size_t)B_ * Q_ * N_ * 2 * D_];// q|k fp16 (later reused for o)
__device__ __half g_vT   [(size_t)NBQ * D_ * N_];        // v transposed fp16 [d][n]
__device__ __half g_S    [(size_t)B_ * Q_ * N_ * N_];    // exp'd scores fp16
__device__ float  g_CP   [(size_t)12 * N_ * N_];         // c_k = (I+DT*A)^k - I, tf32
__device__ float  g_WinT [(size_t)D_ * F_];              // W_in^T  tf32
__device__ float  g_WqkvT[(size_t)3 * D_ * D_];          // Wqkv^T  tf32
__device__ float  g_WoutT[(size_t)F_ * D_];              // W_out^T tf32
__device__ __half g_WoutT16[(size_t)F_ * D_];            // W_out^T fp16
__device__ float  g_WcombT[(size_t)3 * D_ * F_];         // (W_in@Wqkv)^T tf32
__device__ float  g_WioT [(size_t)F_ * F_];              // (W_in@W_out)^T tf32
__device__ float  g_fac  [(size_t)NBQ * N_];             // rowsum(exp), atomic

// ---------------- helpers ----------------------------------------------------
__device__ __forceinline__ uint32_t f2tf32(float f) {
    uint32_t u;
    asm("cvt.rna.tf32.f32 %0, %1;" : "=r"(u) : "f"(f));
    return u;
}
__device__ __forceinline__ float roundtf(float f) { return __uint_as_float(f2tf32(f)); }

__device__ __forceinline__ void mma_tf32(float* c, const uint32_t* a, const uint32_t* b) {
    asm volatile(
        "mma.sync.aligned.m16n8k8.row.col.f32.tf32.tf32.f32 "
        "{%0,%1,%2,%3}, {%4,%5,%6,%7}, {%8,%9}, {%0,%1,%2,%3};"
        : "+f"(c[0]), "+f"(c[1]), "+f"(c[2]), "+f"(c[3])
        : "r"(a[0]), "r"(a[1]), "r"(a[2]), "r"(a[3]),
          "r"(b[0]), "r"(b[1]));
}

__device__ __forceinline__ void mma_f16(float* c, const uint32_t* a, const uint32_t* b) {
    asm volatile(
        "mma.sync.aligned.m16n8k16.row.col.f32.f16.f16.f32 "
        "{%0,%1,%2,%3}, {%4,%5,%6,%7}, {%8,%9}, {%0,%1,%2,%3};"
        : "+f"(c[0]), "+f"(c[1]), "+f"(c[2]), "+f"(c[3])
        : "r"(a[0]), "r"(a[1]), "r"(a[2]), "r"(a[3]),
          "r"(b[0]), "r"(b[1]));
}

__device__ __forceinline__ void ldsm_x4(uint32_t* r, uint32_t addr) {
    asm volatile("ldmatrix.sync.aligned.m8n8.x4.shared.b16 {%0,%1,%2,%3}, [%4];"
                 : "=r"(r[0]), "=r"(r[1]), "=r"(r[2]), "=r"(r[3]) : "r"(addr));
}

__device__ __forceinline__ void cp_async16(uint32_t smem_dst, const void* gsrc) {
    asm volatile("cp.async.cg.shared.global [%0], [%1], 16;\n" :: "r"(smem_dst), "l"(gsrc));
}

// ---------------- K0: fused setup --------------------------------------------
__global__ __launch_bounds__(256) void setup_kernel(const float* __restrict__ in,
                                                    const float* __restrict__ T,
                                                    const float* __restrict__ Win,
                                                    const float* __restrict__ Wq,
                                                    const float* __restrict__ Wk,
                                                    const float* __restrict__ Wv,
                                                    const float* __restrict__ Wout,
                                                    const float* __restrict__ A) {
    __shared__ float Ts[P_][Q_];
    int t = threadIdx.x;
    if (t < P_ * Q_) Ts[t / Q_][t % Q_] = T[t];
    long idx = (long)blockIdx.x * 256 + t;

    if (idx < (long)D_ * D_) {
        int r = (int)(idx / D_), c = (int)(idx % D_);
        g_WqkvT[(long)c * D_ + r]            = roundtf(Wq[idx] * 0.0625f);
        g_WqkvT[(long)(D_ + c) * D_ + r]     = roundtf(Wk[idx]);
        g_WqkvT[(long)(2 * D_ + c) * D_ + r] = roundtf(Wv[idx]);
    }
    if (idx < (long)F_ * D_) {
        int r = (int)(idx / D_), c = (int)(idx % D_);
        g_WinT[(long)c * F_ + r] = roundtf(Win[idx]);
    }
    if (idx < (long)D_ * F_) {
        int r = (int)(idx / F_), c = (int)(idx % F_);
        float w = Wout[idx];
        g_WoutT[(long)c * D_ + r] = roundtf(w);
        g_WoutT16[(long)c * D_ + r] = __float2half_rn(w);
    }
    if (idx < (long)N_ * N_) g_CP[idx] = roundtf(DT_ * A[idx]);
    if (idx < (long)NBQ * N_) g_fac[idx] = 0.f;

    __syncthreads();
    if (idx < (long)B_ * N_ * F_) {
        int f = (int)(idx % F_);
        int n = (int)((idx / F_) % N_);
        int b = (int)(idx / ((long)F_ * N_));
        float vals[P_];
        const float* ip = in + ((long)b * P_ * N_ + n) * F_ + f;
#pragma unroll
        for (int p = 0; p < P_; p++) vals[p] = ip[(long)p * N_ * F_];
        float* op = g_tmp + ((long)b * Q_ * N_ + n) * F_ + f;
#pragma unroll
        for (int q = 0; q < Q_; q++) {
            float s = 0.f;
#pragma unroll
            for (int p = 0; p < P_; p++) s += vals[p] * Ts[p][q];
            op[(long)q * N_ * F_] = roundtf(s);
        }
    }
}

// ---------------- WioT = (W_in @ W_out)^T  (64x64, scalar) --------------------
__global__ __launch_bounds__(256) void wio_kernel() {
    int idx = blockIdx.x * 256 + threadIdx.x;   // 4096 outputs
    if (idx >= F_ * F_) return;
    int j = idx / F_, f = idx % F_;             // WioT[j][f]
    float s = 0.f;
    for (int d = 0; d < D_; d++)
        s += g_WoutT[(long)j * D_ + d] * g_WinT[(long)d * F_ + f];
    g_WioT[idx] = roundtf(s);
}

// ---------------- tf32 GEMM (cp.async x3 + ldmatrix, BK=32) ------------------
template <int BM, int BN, int WM, int WN, bool TRANS_B, bool RESID, int RMOD,
          bool CVT_B, bool ROUND_C, bool RESID2, bool HALF_C, int OCC>
__global__ __launch_bounds__(WM* WN * 32, OCC) void gemm_tc(
    const float* __restrict__ A, const float* __restrict__ Bm,
    void* __restrict__ Cv, const float* __restrict__ R,
    const float* __restrict__ R2,
    int M, int Nn, int K, int lda, int ldb, int ldc, int ldr,
    long sA, long sB, long sC, long sR, float alpha, float beta) {
    constexpr int KBT = 32;
    constexpr int STAGES = 3;
    constexpr int NTH = WM * WN * 32;
    constexpr int WTM = BM / WM, WTN = BN / WN;
    constexpr int FM = WTM / 16, FN = WTN / 8;
    constexpr int KQ = KBT / 4;
    constexpr int LDA_S = KBT + 4;
    constexpr int LDB_S = BN + 8;
    constexpr int NA = BM * KBT / (4 * NTH);
    constexpr int NB = BN * KBT / (4 * NTH);
    constexpr int A_STAGE_B = BM * LDA_S * 4;
    constexpr int BT_STAGE_B = BN * LDA_S * 4;
    constexpr int BN_STAGE_B = KBT * LDB_S * 4;

    extern __shared__ __align__(16) float smem[];
    float* Bs_ = smem + STAGES * BM * LDA_S;
    const uint32_t smem_u32 = (uint32_t)__cvta_generic_to_shared(smem);
    const uint32_t bs_u32 = smem_u32 + STAGES * A_STAGE_B;

    const int bz = blockIdx.z;
    A += (long)bz * sA;
    Bm += (long)bz * sB;
    if (RESID) R += (long)bz * sR;

    const int row0 = blockIdx.y * BM, col0 = blockIdx.x * BN;
    const int tid = threadIdx.x;
    const int lane = tid & 31, wid = tid >> 5;
    const int grp = lane >> 2, qid = lane & 3;
    const int wm = wid / WN, wn = wid % WN;
    const int m_base = wm * WTM, n_base = wn * WTN;

    const int mi = lane >> 3, rr = lane & 7;
    const uint32_t aAddr0 = smem_u32 +
        (((m_base + ((mi & 1) << 3) + rr) * LDA_S + ((mi >> 1) << 2)) << 2);
    const uint32_t bAddr0 = bs_u32 +
        (((n_base + ((mi >> 1) << 3) + rr) * LDA_S + ((mi & 1) << 2)) << 2);

    float acc[FM][FN][4] = {};

    auto issue = [&](int st, int k0) {
#pragma unroll
        for (int l = 0; l < NA; l++) {
            int i = tid + l * NTH;
            int r = i / KQ, kq = i % KQ;
            cp_async16(smem_u32 + st * A_STAGE_B + ((r * LDA_S + kq * 4) << 2),
                       A + (long)(row0 + r) * lda + k0 + kq * 4);
        }
#pragma unroll
        for (int l = 0; l < NB; l++) {
            int i = tid + l * NTH;
            if (!TRANS_B) {
                int kk = i / (BN / 4), nq = i % (BN / 4);
                cp_async16(bs_u32 + st * BN_STAGE_B + ((kk * LDB_S + nq * 4) << 2),
                           Bm + (long)(k0 + kk) * ldb + col0 + nq * 4);
            } else {
                int n = i / KQ, kq = i % KQ;
                cp_async16(bs_u32 + st * BT_STAGE_B + ((n * LDA_S + kq * 4) << 2),
                           Bm + (long)(col0 + n) * ldb + k0 + kq * 4);
            }
        }
    };

    const int kt = K / KBT;
#pragma unroll
    for (int s = 0; s < STAGES - 1; s++) {
        issue(s, s * KBT);
        asm volatile("cp.async.commit_group;\n");
    }

    for (int t = 0; t < kt; t++) {
        asm volatile("cp.async.wait_group %0;\n" :: "n"(STAGES - 2));
        __syncthreads();
        const int st = t % STAGES;
        const int nx = t + STAGES - 1;
        if (nx < kt) issue(nx % STAGES, nx * KBT);
        asm volatile("cp.async.commit_group;\n");

        const uint32_t aSt = aAddr0 + st * A_STAGE_B;
        const uint32_t bSt = bAddr0 + st * BT_STAGE_B;

#pragma unroll
        for (int kc = 0; kc < KBT / 8; kc++) {
            const int kk = kc * 8;
            uint32_t af[FM][4], bf[FN][2];
#pragma unroll
            for (int i = 0; i < FM; i++)
                ldsm_x4(af[i], aSt + i * (16 * LDA_S * 4) + kc * 32);
            if (TRANS_B) {
#pragma unroll
                for (int jp = 0; jp < FN / 2; jp++) {
                    uint32_t tmp4[4];
                    ldsm_x4(tmp4, bSt + jp * (16 * LDA_S * 4) + kc * 32);
                    if (CVT_B) {
#pragma unroll
                        for (int q = 0; q < 4; q++) tmp4[q] = f2tf32(__uint_as_float(tmp4[q]));
                    }
                    bf[jp * 2][0] = tmp4[0]; bf[jp * 2][1] = tmp4[1];
                    bf[jp * 2 + 1][0] = tmp4[2]; bf[jp * 2 + 1][1] = tmp4[3];
                }
            } else {
#pragma unroll
                for (int j = 0; j < FN; j++) {
                    int n = n_base + j * 8 + grp;
                    float b0 = Bs_[(st * KBT + kk + qid) * LDB_S + n];
                    float b1 = Bs_[(st * KBT + kk + qid + 4) * LDB_S + n];
                    bf[j][0] = CVT_B ? f2tf32(b0) : __float_as_uint(b0);
                    bf[j][1] = CVT_B ? f2tf32(b1) : __float_as_uint(b1);
                }
            }
#pragma unroll
            for (int i = 0; i < FM; i++)
#pragma unroll
                for (int j = 0; j < FN; j++) mma_tf32(acc[i][j], af[i], bf[j]);
        }
    }

    float* C = (float*)Cv + (HALF_C ? 0 : (long)bz * sC);
    __half* Ch = (__half*)Cv + (HALF_C ? (long)bz * sC : 0);
#pragma unroll
    for (int i = 0; i < FM; i++) {
        int r0 = row0 + m_base + i * 16 + grp;
#pragma unroll
        for (int j = 0; j < FN; j++) {
            int c = col0 + n_base + j * 8 + qid * 2;
            float2 v0 = {acc[i][j][0] * alpha, acc[i][j][1] * alpha};
            float2 v1 = {acc[i][j][2] * alpha, acc[i][j][3] * alpha};
            if (RESID) {
                int rr0 = RMOD ? (r0 % RMOD) : r0;
                int rr1 = RMOD ? ((r0 + 8) % RMOD) : (r0 + 8);
                float2 r0v = *(const float2*)(R + (long)rr0 * ldr + c);
                float2 r1v = *(const float2*)(R + (long)rr1 * ldr + c);
                v0.x += beta * r0v.x; v0.y += beta * r0v.y;
                v1.x += beta * r1v.x; v1.y += beta * r1v.y;
            }
            if (RESID2) {
                float2 a0 = *(const float2*)(R2 + (long)(r0 % N_) * N_ + c);
                float2 a1 = *(const float2*)(R2 + (long)((r0 + 8) % N_) * N_ + c);
                v0.x += a0.x; v0.y += a0.y;
                v1.x += a1.x; v1.y += a1.y;
            }
            if (HALF_C) {
                *(__half2*)(Ch + (long)r0 * ldc + c) = __floats2half2_rn(v0.x, v0.y);
                *(__half2*)(Ch + (long)(r0 + 8) * ldc + c) = __floats2half2_rn(v1.x, v1.y);
            } else {
                if (ROUND_C) {
                    v0.x = roundtf(v0.x); v0.y = roundtf(v0.y);
                    v1.x = roundtf(v1.x); v1.y = roundtf(v1.y);
                }
                *(float2*)(C + (long)r0 * ldc + c) = v0;
                *(float2*)(C + (long)(r0 + 8) * ldc + c) = v1;
            }
        }
    }
}

// ---------------- fp16 NT GEMM (m16n8k16, cp.async x3, KBT=64 halves) --------
// A: M x K fp16 (lda). B: Nn x K fp16 (ldb). C = A*B^T.
// EXPC: out = exp(acc-EXPSHIFT) fp16; SUMS: rowsums -> atomicAdd fac.
// FACE: rows scaled by 1/fac; H16OUT: fp16 out; RESID: +R fp32, fp32 out (no round).
template <int BM, int BN, bool EXPC, bool SUMS, bool FACE, bool RESID, bool H16OUT, int OCC>
__global__ __launch_bounds__(256, OCC) void gemm_f16(
    const __half* __restrict__ A, const __half* __restrict__ Bm,
    void* __restrict__ Cv, const float* __restrict__ R, float* __restrict__ fac,
    int M, int Nn, int K, int lda, int ldb, int ldc, int ldr,
    long sA, long sB, long sC, long sR) {
    constexpr int KBT = 64;                 // halves per k-tile
    constexpr int STAGES = 3;
    constexpr int NTH = 256;
    constexpr int WN = 4;
    constexpr int WTM = BM / 2, WTN = BN / WN;
    constexpr int FM = WTM / 16, FN = WTN / 8;
    constexpr int LDH = KBT + 8;            // 72 halves = 36 words: conflict-free
    constexpr int KQ = KBT / 8;             // 16B chunks per row (8)
    constexpr int NA = BM * KBT / (8 * NTH);
    constexpr int NB = BN * KBT / (8 * NTH);
    constexpr int A_STAGE_B = BM * LDH * 2;
    constexpr int B_STAGE_B = BN * LDH * 2;

    extern __shared__ __align__(16) __half hsm[];
    const uint32_t smem_u32 = (uint32_t)__cvta_generic_to_shared(hsm);
    const uint32_t bs_u32 = smem_u32 + STAGES * A_STAGE_B;

    const int bz = blockIdx.z;
    A += (long)bz * sA;
    Bm += (long)bz * sB;
    if (RESID) R += (long)bz * sR;

    const int row0 = blockIdx.y * BM, col0 = blockIdx.x * BN;
    const int tid = threadIdx.x;
    const int lane = tid & 31, wid = tid >> 5;
    const int grp = lane >> 2, qid = lane & 3;
    const int wm = wid / WN, wn = wid % WN;
    const int m_base = wm * WTM, n_base = wn * WTN;

    const int l16 = lane & 15, lh = lane >> 4;
    const uint32_t aAddr0 = smem_u32 + (((m_base + l16) * LDH + lh * 8) << 1);
    const uint32_t bAddr0 = bs_u32 + (((n_base + l16) * LDH + lh * 8) << 1);

    float acc[FM][FN][4] = {};

    auto issue = [&](int st, int k0) {
#pragma unroll
        for (int l = 0; l < NA; l++) {
            int i = tid + l * NTH;
            int r = i / KQ, kq = i % KQ;
            cp_async16(smem_u32 + st * A_STAGE_B + ((r * LDH + kq * 8) << 1),
                       A + (long)(row0 + r) * lda + k0 + kq * 8);
        }
#pragma unroll
        for (int l = 0; l < NB; l++) {
            int i = tid + l * NTH;
            int n = i / KQ, kq = i % KQ;
            cp_async16(bs_u32 + st * B_STAGE_B + ((n * LDH + kq * 8) << 1),
                       Bm + (long)(col0 + n) * ldb + k0 + kq * 8);
        }
    };

    const int kt = K / KBT;
#pragma unroll
    for (int s = 0; s < STAGES - 1; s++) {
        if (s < kt) issue(s, s * KBT);
        asm volatile("cp.async.commit_group;\n");
    }

    for (int t = 0; t < kt; t++) {
        asm volatile("cp.async.wait_group %0;\n" :: "n"(STAGES - 2));
        __syncthreads();
        const int st = t % STAGES;
        const int nx = t + STAGES - 1;
        if (nx < kt) issue(nx % STAGES, nx * KBT);
        asm volatile("cp.async.commit_group;\n");

        const uint32_t aSt = aAddr0 + st * A_STAGE_B;
        const uint32_t bSt = bAddr0 + st * B_STAGE_B;

#pragma unroll
        for (int kc = 0; kc < KBT / 16; kc++) {      // k16 chunks
            uint32_t af[FM][4], bf[FN][2];
#pragma unroll
            for (int i = 0; i < FM; i++)
                ldsm_x4(af[i], aSt + i * (16 * LDH * 2) + kc * 32);
#pragma unroll
            for (int jp = 0; jp < FN / 2; jp++) {
                uint32_t t4[4];
                ldsm_x4(t4, bSt + jp * (16 * LDH * 2) + kc * 32);
                bf[jp * 2][0] = t4[0];     bf[jp * 2][1] = t4[2];
                bf[jp * 2 + 1][0] = t4[1]; bf[jp * 2 + 1][1] = t4[3];
            }
#pragma unroll
            for (int i = 0; i < FM; i++)
#pragma unroll
                for (int j = 0; j < FN; j++) mma_f16(acc[i][j], af[i], bf[j]);
        }
    }

    __half* Ch = (__half*)Cv + ((EXPC || H16OUT) ? (long)bz * sC : 0);
    float* Cf = (float*)Cv + ((EXPC || H16OUT) ? 0 : (long)bz * sC);
    float facr[FM][2];
    if (FACE) {
        const float* fb = fac + (long)bz * M + row0 + m_base + grp;
#pragma unroll
        for (int i = 0; i < FM; i++) {
            facr[i][0] = 1.f / fb[i * 16];
            facr[i][1] = 1.f / fb[i * 16 + 8];
        }
    }
    float rs[FM][2];
    if (SUMS) {
#pragma unroll
        for (int i = 0; i < FM; i++) { rs[i][0] = 0.f; rs[i][1] = 0.f; }
    }
#pragma unroll
    for (int i = 0; i < FM; i++) {
        int r0 = row0 + m_base + i * 16 + grp;
#pragma unroll
        for (int j = 0; j < FN; j++) {
            int c = col0 + n_base + j * 8 + qid * 2;
            if (EXPC) {
                __half h00 = __float2half_rn(__expf(acc[i][j][0] - EXPSHIFT));
                __half h01 = __float2half_rn(__expf(acc[i][j][1] - EXPSHIFT));
                __half h10 = __float2half_rn(__expf(acc[i][j][2] - EXPSHIFT));
                __half h11 = __float2half_rn(__expf(acc[i][j][3] - EXPSHIFT));
                if (SUMS) {
                    rs[i][0] += __half2float(h00) + __half2float(h01);
                    rs[i][1] += __half2float(h10) + __half2float(h11);
                }
                *(__half2*)(Ch + (long)r0 * ldc + c) = __halves2half2(h00, h01);
                *(__half2*)(Ch + (long)(r0 + 8) * ldc + c) = __halves2half2(h10, h11);
            } else {
                float2 v0 = {acc[i][j][0], acc[i][j][1]};
                float2 v1 = {acc[i][j][2], acc[i][j][3]};
                if (FACE) {
                    v0.x *= facr[i][0]; v0.y *= facr[i][0];
                    v1.x *= facr[i][1]; v1.y *= facr[i][1];
                }
                if (H16OUT) {
                    *(__half2*)(Ch + (long)r0 * ldc + c) = __floats2half2_rn(v0.x, v0.y);
                    *(__half2*)(Ch + (long)(r0 + 8) * ldc + c) = __floats2half2_rn(v1.x, v1.y);
                } else {
                    if (RESID) {
                        float2 r0v = *(const float2*)(R + (long)r0 * ldr + c);
                        float2 r1v = *(const float2*)(R + (long)(r0 + 8) * ldr + c);
                        v0.x += r0v.x; v0.y += r0v.y;
                        v1.x += r1v.x; v1.y += r1v.y;
                    }
                    *(float2*)(Cf + (long)r0 * ldc + c) = v0;
                    *(float2*)(Cf + (long)(r0 + 8) * ldc + c) = v1;
                }
            }
        }
    }
    if (SUMS) {
#pragma unroll
        for (int i = 0; i < FM; i++)
#pragma unroll
            for (int h = 0; h < 2; h++) {
                float s = rs[i][h];
                s += __shfl_xor_sync(0xffffffffu, s, 1);
                s += __shfl_xor_sync(0xffffffffu, s, 2);
                if (qid == 0)
                    atomicAdd(fac + (long)bz * M + row0 + m_base + i * 16 + grp + h * 8, s);
            }
    }
}

// host-side smem mirrors
static inline int gemm_smem_bytes(int BM, int BN, bool transB) {
    const int STAGES = 3, KBT = 32, LDA_S = KBT + 4;
    int a = STAGES * BM * LDA_S;
    int b = transB ? STAGES * BN * LDA_S : STAGES * KBT * (BN + 8);
    return (a + b) * 4;
}
static inline int gemm_f16_smem_bytes(int BM, int BN) {
    const int STAGES = 3, LDH = 72;
    return STAGES * (BM + BN) * LDH * 2;
}

// ---------------- launch ----------------------------------------------------
extern "C" void kernel_launch(void* const* d_in, const int* in_sizes, int n_in,
                              void* d_out, int out_size) {
    const float* inputs = (const float*)d_in[0];
    const float* W_in  = (const float*)d_in[2];
    const float* T_mix = (const float*)d_in[3];
    const float* Wq    = (const float*)d_in[4];
    const float* Wk    = (const float*)d_in[5];
    const float* Wv    = (const float*)d_in[6];
    const float* W_out = (const float*)d_in[7];
    const float* A     = (const float*)d_in[8];

    float* out = (float*)d_out;
    float* mgt = out;
    float* kal = out + (long)B_ * Q_ * N_ * F_;

    float *tmp, *CP, *WinT, *WqkvT, *WoutT, *WcombT, *WioT, *fac;
    __half *qk, *vT, *S, *WoutT16;
    cudaGetSymbolAddress((void**)&tmp, g_tmp);
    cudaGetSymbolAddress((void**)&qk, g_qk);
    cudaGetSymbolAddress((void**)&vT, g_vT);
    cudaGetSymbolAddress((void**)&S, g_S);
    cudaGetSymbolAddress((void**)&CP, g_CP);
    cudaGetSymbolAddress((void**)&WinT, g_WinT);
    cudaGetSymbolAddress((void**)&WqkvT, g_WqkvT);
    cudaGetSymbolAddress((void**)&WoutT, g_WoutT);
    cudaGetSymbolAddress((void**)&WoutT16, g_WoutT16);
    cudaGetSymbolAddress((void**)&WcombT, g_WcombT);
    cudaGetSymbolAddress((void**)&WioT, g_WioT);
    cudaGetSymbolAddress((void**)&fac, g_fac);

    const long sNN = (long)N_ * N_;
    const long sNF = (long)N_ * F_;
    const long sQK = (long)N_ * 2 * D_;
    const long sVT = (long)D_ * N_;
    const long sO  = (long)N_ * D_;       // o stride in qk buffer (halves)

    // tf32 instances
    auto kQKP  = gemm_tc<128, 128, 2, 4, true,  false, 0,  false, false, false, true,  2>;
    auto kVT   = gemm_tc<128, 128, 2, 4, true,  false, 0,  false, false, false, true,  2>;
    auto kMG0  = gemm_tc<128, 64,  2, 2, true,  false, 0,  false, false, false, false, 2>;
    auto kWC   = gemm_tc<128, 64,  2, 2, false, false, 0,  false, true,  false, false, 2>;
    auto kCP   = gemm_tc<128, 128, 2, 4, false, true,  0,  false, true,  true,  false, 2>;
    auto kKAL  = gemm_tc<128, 64,  2, 2, false, true,  N_, true,  false, false, false, 2>;
    // fp16 instances
    auto kQK16 = gemm_f16<128, 128, true,  true,  false, false, false, 2>;   // K4
    auto kAV16 = gemm_f16<128, 128, false, false, true,  false, true,  2>;   // K6 -> o fp16
    auto kMGT  = gemm_f16<128, 64,  false, false, false, true,  false, 2>;   // K7b

    const int smNT    = gemm_smem_bytes(128, 128, true);
    const int smNN    = gemm_smem_bytes(128, 128, false);
    const int smNT64  = gemm_smem_bytes(128, 64, true);
    const int smNN64  = gemm_smem_bytes(128, 64, false);
    const int smF16   = gemm_f16_smem_bytes(128, 128);
    const int smF1664 = gemm_f16_smem_bytes(128, 64);
    cudaFuncSetAttribute(kQKP,  cudaFuncAttributeMaxDynamicSharedMemorySize, smNT);
    cudaFuncSetAttribute(kVT,   cudaFuncAttributeMaxDynamicSharedMemorySize, smNT);
    cudaFuncSetAttribute(kMG0,  cudaFuncAttributeMaxDynamicSharedMemorySize, smNT64);
    cudaFuncSetAttribute(kWC,   cudaFuncAttributeMaxDynamicSharedMemorySize, smNN64);
    cudaFuncSetAttribute(kCP,   cudaFuncAttributeMaxDynamicSharedMemorySize, smNN);
    cudaFuncSetAttribute(kKAL,  cudaFuncAttributeMaxDynamicSharedMemorySize, smNN64);
    cudaFuncSetAttribute(kQK16, cudaFuncAttributeMaxDynamicSharedMemorySize, smF16);
    cudaFuncSetAttribute(kAV16, cudaFuncAttributeMaxDynamicSharedMemorySize, smF16);
    cudaFuncSetAttribute(kMGT,  cudaFuncAttributeMaxDynamicSharedMemorySize, smF1664);

    // setup + tiny weight combos
    setup_kernel<<<((long)B_ * N_ * F_ + 255) / 256, 256>>>(
        inputs, T_mix, W_in, Wq, Wk, Wv, W_out, A);
    wio_kernel<<<(F_ * F_ + 255) / 256, 256>>>();
    kWC<<<dim3(1, 3 * D_ / 128, 1), 128, smNN64>>>(
        WqkvT, WinT, WcombT, nullptr, nullptr,
        3 * D_, F_, D_, D_, F_, F_, 0, 0, 0, 0, 0, 1.f, 0.f);

    // qk = tmp @ Wcomb_qk^T (K=64, fp16 out)
    kQKP<<<dim3(4, BQN / 128, 1), 256, smNT>>>(
        tmp, WcombT, qk, nullptr, nullptr,
        BQN, 2 * D_, F_, F_, F_, 2 * D_, 0, 0, 0, 0, 0, 1.f, 0.f);

    // K4: S = exp(q@k^T - 8) fp16, rowsums -> fac   (profiled launch)
    kQK16<<<dim3(4, 4, NBQ), 256, smF16>>>(
        qk, qk + D_, S, nullptr, fac,
        N_, N_, D_, 2 * D_, 2 * D_, N_, 0, sQK, sQK, sNN, 0);

    // vT[bq] = Wcomb_v @ tmp[bq]^T (fp16)
    kVT<<<dim3(4, 2, NBQ), 256, smNT>>>(
        WcombT + (long)2 * D_ * F_, tmp, vT, nullptr, nullptr,
        D_, N_, F_, F_, F_, N_, 0, 0, (long)N_ * F_, sVT, 0, 1.f, 0.f);

    // K6: o = (S @ vT^T) * (1/rowsum), fp16 out into qk buffer
    kAV16<<<dim3(2, 4, NBQ), 256, smF16>>>(
        S, vT, qk, nullptr, fac,
        N_, D_, N_, N_, N_, D_, 0, sNN, sVT, sO, 0);

    // K7a: mgt0 = tmp @ WioT^T  (K=64, fp32)
    kMG0<<<dim3(1, BQN / 128, 1), 128, smNT64>>>(
        tmp, WioT, mgt, nullptr, nullptr,
        BQN, F_, F_, F_, F_, F_, 0, 0, 0, 0, 0, 1.f, 0.f);

    // K7b: mgt = o @ WoutT16^T + mgt0  (fp16 GEMM, fp32 residual/out)
    kMGT<<<dim3(1, BQN / 128, 1), 256, smF1664>>>(
        qk, WoutT16, mgt, mgt, nullptr,
        BQN, F_, D_, D_, D_, F_, F_, 0, 0, 0, 0);

    // CP chain: c_{k+j} = c_k @ c_j + c_k + c_j
    float* c1 = CP;
    float* c2 = CP + sNN;
    float* c4 = CP + 3 * sNN;
    float* c8 = CP + 7 * sNN;
    kCP<<<dim3(4, 4, 1), 256, smNN>>>(c1, c1, c2, c1, c1,
        N_, N_, N_, N_, N_, N_, N_, 0, 0, 0, 0, 1.f, 1.f);
    kCP<<<dim3(4, 8, 1), 256, smNN>>>(CP, c2, CP + 2 * sNN, CP, c2,
        2 * N_, N_, N_, N_, N_, N_, N_, 0, 0, 0, 0, 1.f, 1.f);
    kCP<<<dim3(4, 16, 1), 256, smNN>>>(CP, c4, CP + 4 * sNN, CP, c4,
        4 * N_, N_, N_, N_, N_, N_, N_, 0, 0, 0, 0, 1.f, 1.f);
    kCP<<<dim3(4, 16, 1), 256, smNN>>>(CP, c8, CP + 8 * sNN, CP, c8,
        4 * N_, N_, N_, N_, N_, N_, N_, 0, 0, 0, 0, 1.f, 1.f);

    // Kalman: kal[b, t] = c_{t+1} @ mu0[b] + mu0[b]
    const float* mu0 = inputs + (long)(P_ - 1) * sNF;
    kKAL<<<dim3(1, 12 * N_ / 128, B_), 128, smNN64>>>(
        CP, mu0, kal, mu0, nullptr,
        12 * N_, F_, N_, N_, F_, F_, F_,
        0, (long)P_ * sNF, (long)Q_ * sNF, (long)P_ * sNF, 1.f, 1.f);
}

// round 16
// speedup vs baseline: 1.8677x; 1.0637x over previous
#include <cuda_runtime.h>
#include <cuda_fp16.h>
#include <cstdint>

// Problem dims
#define B_ 32
#define P_ 12
#define N_ 512
#define F_ 64
#define D_ 256
#define Q_ 12
#define DT_ 0.1f

static const int BQN = B_ * Q_ * N_;  // 196608
#define NBQ (B_ * Q_)                 // 384
#define EXPSHIFT 8.0f                 // softmax shift (cancels in normalization)
#define LDCAT 320                     // cat row: [tmp16 (64) | o (256)]

// ---------------- scratch (device globals; no runtime alloc) ----------------
__device__ __half g_cat  [(size_t)B_ * Q_ * N_ * LDCAT]; // [tmp16 | o]
__device__ __half g_qk   [(size_t)B_ * Q_ * N_ * 2 * D_];// q|k fp16, ld=512
__device__ __half g_vT   [(size_t)NBQ * D_ * N_];        // v transposed fp16 [d][n]
__device__ __half g_S    [(size_t)B_ * Q_ * N_ * N_];    // exp'd scores fp16
__device__ float  g_CP   [(size_t)12 * N_ * N_];         // c_k = (I+DT*A)^k - I, tf32
__device__ float  g_WinT [(size_t)D_ * F_];              // W_in^T  tf32
__device__ float  g_WqkvT[(size_t)3 * D_ * D_];          // Wqkv^T  tf32
__device__ float  g_WoutT[(size_t)F_ * D_];              // W_out^T tf32
__device__ __half g_WcombT16[(size_t)3 * D_ * F_];       // (W_in@Wqkv)^T fp16
__device__ __half g_Wcat16[(size_t)F_ * LDCAT];          // [WioT | WoutT] fp16
__device__ float  g_fac  [(size_t)NBQ * N_];             // rowsum(exp), atomic

// ---------------- helpers ----------------------------------------------------
__device__ __forceinline__ uint32_t f2tf32(float f) {
    uint32_t u;
    asm("cvt.rna.tf32.f32 %0, %1;" : "=r"(u) : "f"(f));
    return u;
}
__device__ __forceinline__ float roundtf(float f) { return __uint_as_float(f2tf32(f)); }

__device__ __forceinline__ void mma_tf32(float* c, const uint32_t* a, const uint32_t* b) {
    asm volatile(
        "mma.sync.aligned.m16n8k8.row.col.f32.tf32.tf32.f32 "
        "{%0,%1,%2,%3}, {%4,%5,%6,%7}, {%8,%9}, {%0,%1,%2,%3};"
        : "+f"(c[0]), "+f"(c[1]), "+f"(c[2]), "+f"(c[3])
        : "r"(a[0]), "r"(a[1]), "r"(a[2]), "r"(a[3]),
          "r"(b[0]), "r"(b[1]));
}

__device__ __forceinline__ void mma_f16(float* c, const uint32_t* a, const uint32_t* b) {
    asm volatile(
        "mma.sync.aligned.m16n8k16.row.col.f32.f16.f16.f32 "
        "{%0,%1,%2,%3}, {%4,%5,%6,%7}, {%8,%9}, {%0,%1,%2,%3};"
        : "+f"(c[0]), "+f"(c[1]), "+f"(c[2]), "+f"(c[3])
        : "r"(a[0]), "r"(a[1]), "r"(a[2]), "r"(a[3]),
          "r"(b[0]), "r"(b[1]));
}

__device__ __forceinline__ void ldsm_x4(uint32_t* r, uint32_t addr) {
    asm volatile("ldmatrix.sync.aligned.m8n8.x4.shared.b16 {%0,%1,%2,%3}, [%4];"
                 : "=r"(r[0]), "=r"(r[1]), "=r"(r[2]), "=r"(r[3]) : "r"(addr));
}

__device__ __forceinline__ void cp_async16(uint32_t smem_dst, const void* gsrc) {
    asm volatile("cp.async.cg.shared.global [%0], [%1], 16;\n" :: "r"(smem_dst), "l"(gsrc));
}

// ---------------- K0: fused setup --------------------------------------------
__global__ __launch_bounds__(256) void setup_kernel(const float* __restrict__ in,
                                                    const float* __restrict__ T,
                                                    const float* __restrict__ Win,
                                                    const float* __restrict__ Wq,
                                                    const float* __restrict__ Wk,
                                                    const float* __restrict__ Wv,
                                                    const float* __restrict__ Wout,
                                                    const float* __restrict__ A) {
    __shared__ float Ts[P_][Q_];
    int t = threadIdx.x;
    if (t < P_ * Q_) Ts[t / Q_][t % Q_] = T[t];
    long idx = (long)blockIdx.x * 256 + t;

    if (idx < (long)D_ * D_) {
        int r = (int)(idx / D_), c = (int)(idx % D_);
        g_WqkvT[(long)c * D_ + r]            = roundtf(Wq[idx] * 0.0625f);
        g_WqkvT[(long)(D_ + c) * D_ + r]     = roundtf(Wk[idx]);
        g_WqkvT[(long)(2 * D_ + c) * D_ + r] = roundtf(Wv[idx]);
    }
    if (idx < (long)F_ * D_) {
        int r = (int)(idx / D_), c = (int)(idx % D_);
        g_WinT[(long)c * F_ + r] = roundtf(Win[idx]);
    }
    if (idx < (long)D_ * F_) {
        int r = (int)(idx / F_), c = (int)(idx % F_);
        g_WoutT[(long)c * D_ + r] = Wout[idx];
    }
    if (idx < (long)N_ * N_) g_CP[idx] = roundtf(DT_ * A[idx]);
    if (idx < (long)NBQ * N_) g_fac[idx] = 0.f;

    __syncthreads();
    if (idx < (long)B_ * N_ * F_) {
        int f = (int)(idx % F_);
        int n = (int)((idx / F_) % N_);
        int b = (int)(idx / ((long)F_ * N_));
        float vals[P_];
        const float* ip = in + ((long)b * P_ * N_ + n) * F_ + f;
#pragma unroll
        for (int p = 0; p < P_; p++) vals[p] = ip[(long)p * N_ * F_];
        __half* op = g_cat + ((long)b * Q_ * N_ + n) * LDCAT + f;
#pragma unroll
        for (int q = 0; q < Q_; q++) {
            float s = 0.f;
#pragma unroll
            for (int p = 0; p < P_; p++) s += vals[p] * Ts[p][q];
            op[(long)q * N_ * LDCAT] = __float2half_rn(s);
        }
    }
}

// ---------------- Wcat = [ (W_in@W_out)^T | W_out^T ] fp16 --------------------
__global__ __launch_bounds__(256) void wcat_kernel() {
    int idx = blockIdx.x * 256 + threadIdx.x;
    if (idx < F_ * F_) {                 // WioT part: Wcat[j][f] = sum_d WoutT[j][d]*WinT[d][f]
        int j = idx / F_, f = idx % F_;
        float s = 0.f;
        for (int d = 0; d < D_; d++)
            s += g_WoutT[(long)j * D_ + d] * g_WinT[(long)d * F_ + f];
        g_Wcat16[(long)j * LDCAT + f] = __float2half_rn(s);
    }
    if (idx < F_ * D_) {                 // WoutT part: Wcat[j][64+d] = WoutT[j][d]
        int j = idx / D_, d = idx % D_;
        g_Wcat16[(long)j * LDCAT + F_ + d] = __float2half_rn(g_WoutT[(long)j * D_ + d]);
    }
}

// ---------------- tf32 GEMM (cp.async x3 + ldmatrix, BK=32) ------------------
template <int BM, int BN, int WM, int WN, bool TRANS_B, bool RESID, int RMOD,
          bool CVT_B, bool ROUND_C, bool RESID2, bool HALF_C, int OCC>
__global__ __launch_bounds__(WM* WN * 32, OCC) void gemm_tc(
    const float* __restrict__ A, const float* __restrict__ Bm,
    void* __restrict__ Cv, const float* __restrict__ R,
    const float* __restrict__ R2,
    int M, int Nn, int K, int lda, int ldb, int ldc, int ldr,
    long sA, long sB, long sC, long sR, float alpha, float beta) {
    constexpr int KBT = 32;
    constexpr int STAGES = 3;
    constexpr int NTH = WM * WN * 32;
    constexpr int WTM = BM / WM, WTN = BN / WN;
    constexpr int FM = WTM / 16, FN = WTN / 8;
    constexpr int KQ = KBT / 4;
    constexpr int LDA_S = KBT + 4;
    constexpr int LDB_S = BN + 8;
    constexpr int NA = BM * KBT / (4 * NTH);
    constexpr int NB = BN * KBT / (4 * NTH);
    constexpr int A_STAGE_B = BM * LDA_S * 4;
    constexpr int BT_STAGE_B = BN * LDA_S * 4;
    constexpr int BN_STAGE_B = KBT * LDB_S * 4;

    extern __shared__ __align__(16) float smem[];
    float* Bs_ = smem + STAGES * BM * LDA_S;
    const uint32_t smem_u32 = (uint32_t)__cvta_generic_to_shared(smem);
    const uint32_t bs_u32 = smem_u32 + STAGES * A_STAGE_B;

    const int bz = blockIdx.z;
    A += (long)bz * sA;
    Bm += (long)bz * sB;
    if (RESID) R += (long)bz * sR;

    const int row0 = blockIdx.y * BM, col0 = blockIdx.x * BN;
    const int tid = threadIdx.x;
    const int lane = tid & 31, wid = tid >> 5;
    const int grp = lane >> 2, qid = lane & 3;
    const int wm = wid / WN, wn = wid % WN;
    const int m_base = wm * WTM, n_base = wn * WTN;

    const int mi = lane >> 3, rr = lane & 7;
    const uint32_t aAddr0 = smem_u32 +
        (((m_base + ((mi & 1) << 3) + rr) * LDA_S + ((mi >> 1) << 2)) << 2);
    const uint32_t bAddr0 = bs_u32 +
        (((n_base + ((mi >> 1) << 3) + rr) * LDA_S + ((mi & 1) << 2)) << 2);

    float acc[FM][FN][4] = {};

    auto issue = [&](int st, int k0) {
#pragma unroll
        for (int l = 0; l < NA; l++) {
            int i = tid + l * NTH;
            int r = i / KQ, kq = i % KQ;
            cp_async16(smem_u32 + st * A_STAGE_B + ((r * LDA_S + kq * 4) << 2),
                       A + (long)(row0 + r) * lda + k0 + kq * 4);
        }
#pragma unroll
        for (int l = 0; l < NB; l++) {
            int i = tid + l * NTH;
            if (!TRANS_B) {
                int kk = i / (BN / 4), nq = i % (BN / 4);
                cp_async16(bs_u32 + st * BN_STAGE_B + ((kk * LDB_S + nq * 4) << 2),
                           Bm + (long)(k0 + kk) * ldb + col0 + nq * 4);
            } else {
                int n = i / KQ, kq = i % KQ;
                cp_async16(bs_u32 + st * BT_STAGE_B + ((n * LDA_S + kq * 4) << 2),
                           Bm + (long)(col0 + n) * ldb + k0 + kq * 4);
            }
        }
    };

    const int kt = K / KBT;
#pragma unroll
    for (int s = 0; s < STAGES - 1; s++) {
        if (s < kt) issue(s, s * KBT);
        asm volatile("cp.async.commit_group;\n");
    }

    for (int t = 0; t < kt; t++) {
        asm volatile("cp.async.wait_group %0;\n" :: "n"(STAGES - 2));
        __syncthreads();
        const int st = t % STAGES;
        const int nx = t + STAGES - 1;
        if (nx < kt) issue(nx % STAGES, nx * KBT);
        asm volatile("cp.async.commit_group;\n");

        const uint32_t aSt = aAddr0 + st * A_STAGE_B;
        const uint32_t bSt = bAddr0 + st * BT_STAGE_B;

#pragma unroll
        for (int kc = 0; kc < KBT / 8; kc++) {
            const int kk = kc * 8;
            uint32_t af[FM][4], bf[FN][2];
#pragma unroll
            for (int i = 0; i < FM; i++)
                ldsm_x4(af[i], aSt + i * (16 * LDA_S * 4) + kc * 32);
            if (TRANS_B) {
#pragma unroll
                for (int jp = 0; jp < FN / 2; jp++) {
                    uint32_t tmp4[4];
                    ldsm_x4(tmp4, bSt + jp * (16 * LDA_S * 4) + kc * 32);
                    if (CVT_B) {
#pragma unroll
                        for (int q = 0; q < 4; q++) tmp4[q] = f2tf32(__uint_as_float(tmp4[q]));
                    }
                    bf[jp * 2][0] = tmp4[0]; bf[jp * 2][1] = tmp4[1];
                    bf[jp * 2 + 1][0] = tmp4[2]; bf[jp * 2 + 1][1] = tmp4[3];
                }
            } else {
#pragma unroll
                for (int j = 0; j < FN; j++) {
                    int n = n_base + j * 8 + grp;
                    float b0 = Bs_[(st * KBT + kk + qid) * LDB_S + n];
                    float b1 = Bs_[(st * KBT + kk + qid + 4) * LDB_S + n];
                    bf[j][0] = CVT_B ? f2tf32(b0) : __float_as_uint(b0);
                    bf[j][1] = CVT_B ? f2tf32(b1) : __float_as_uint(b1);
                }
            }
#pragma unroll
            for (int i = 0; i < FM; i++)
#pragma unroll
                for (int j = 0; j < FN; j++) mma_tf32(acc[i][j], af[i], bf[j]);
        }
    }

    float* C = (float*)Cv + (HALF_C ? 0 : (long)bz * sC);
    __half* Ch = (__half*)Cv + (HALF_C ? (long)bz * sC : 0);
#pragma unroll
    for (int i = 0; i < FM; i++) {
        int r0 = row0 + m_base + i * 16 + grp;
#pragma unroll
        for (int j = 0; j < FN; j++) {
            int c = col0 + n_base + j * 8 + qid * 2;
            float2 v0 = {acc[i][j][0] * alpha, acc[i][j][1] * alpha};
            float2 v1 = {acc[i][j][2] * alpha, acc[i][j][3] * alpha};
            if (RESID) {
                int rr0 = RMOD ? (r0 % RMOD) : r0;
                int rr1 = RMOD ? ((r0 + 8) % RMOD) : (r0 + 8);
                float2 r0v = *(const float2*)(R + (long)rr0 * ldr + c);
                float2 r1v = *(const float2*)(R + (long)rr1 * ldr + c);
                v0.x += beta * r0v.x; v0.y += beta * r0v.y;
                v1.x += beta * r1v.x; v1.y += beta * r1v.y;
            }
            if (RESID2) {
                float2 a0 = *(const float2*)(R2 + (long)(r0 % N_) * N_ + c);
                float2 a1 = *(const float2*)(R2 + (long)((r0 + 8) % N_) * N_ + c);
                v0.x += a0.x; v0.y += a0.y;
                v1.x += a1.x; v1.y += a1.y;
            }
            if (HALF_C) {
                *(__half2*)(Ch + (long)r0 * ldc + c) = __floats2half2_rn(v0.x, v0.y);
                *(__half2*)(Ch + (long)(r0 + 8) * ldc + c) = __floats2half2_rn(v1.x, v1.y);
            } else {
                if (ROUND_C) {
                    v0.x = roundtf(v0.x); v0.y = roundtf(v0.y);
                    v1.x = roundtf(v1.x); v1.y = roundtf(v1.y);
                }
                *(float2*)(C + (long)r0 * ldc + c) = v0;
                *(float2*)(C + (long)(r0 + 8) * ldc + c) = v1;
            }
        }
    }
}

// ---------------- fp16 NT GEMM (m16n8k16, cp.async x3, KBT=64 halves) --------
// A: M x K fp16 (lda). B: Nn x K fp16 (ldb). C = A*B^T.
// EXPC: out = exp(acc-EXPSHIFT) fp16; SUMS: rowsums -> atomicAdd fac.
// FACE: rows scaled by 1/fac; H16OUT: fp16 out; else fp32 out (no residual).
template <int BM, int BN, bool EXPC, bool SUMS, bool FACE, bool H16OUT, int OCC>
__global__ __launch_bounds__(256, OCC) void gemm_f16(
    const __half* __restrict__ A, const __half* __restrict__ Bm,
    void* __restrict__ Cv, float* __restrict__ fac,
    int M, int Nn, int K, int lda, int ldb, int ldc,
    long sA, long sB, long sC) {
    constexpr int KBT = 64;
    constexpr int STAGES = 3;
    constexpr int NTH = 256;
    constexpr int WN = 4;
    constexpr int WTM = BM / 2, WTN = BN / WN;
    constexpr int FM = WTM / 16, FN = WTN / 8;
    constexpr int LDH = KBT + 8;            // 72 halves: conflict-free
    constexpr int KQ = KBT / 8;
    constexpr int NA = BM * KBT / (8 * NTH);
    constexpr int NB = BN * KBT / (8 * NTH);
    constexpr int A_STAGE_B = BM * LDH * 2;
    constexpr int B_STAGE_B = BN * LDH * 2;

    extern __shared__ __align__(16) __half hsm[];
    const uint32_t smem_u32 = (uint32_t)__cvta_generic_to_shared(hsm);
    const uint32_t bs_u32 = smem_u32 + STAGES * A_STAGE_B;

    const int bz = blockIdx.z;
    A += (long)bz * sA;
    Bm += (long)bz * sB;

    const int row0 = blockIdx.y * BM, col0 = blockIdx.x * BN;
    const int tid = threadIdx.x;
    const int lane = tid & 31, wid = tid >> 5;
    const int grp = lane >> 2, qid = lane & 3;
    const int wm = wid / WN, wn = wid % WN;
    const int m_base = wm * WTM, n_base = wn * WTN;

    const int l16 = lane & 15, lh = lane >> 4;
    const uint32_t aAddr0 = smem_u32 + (((m_base + l16) * LDH + lh * 8) << 1);
    const uint32_t bAddr0 = bs_u32 + (((n_base + l16) * LDH + lh * 8) << 1);

    float acc[FM][FN][4] = {};

    auto issue = [&](int st, int k0) {
#pragma unroll
        for (int l = 0; l < NA; l++) {
            int i = tid + l * NTH;
            int r = i / KQ, kq = i % KQ;
            cp_async16(smem_u32 + st * A_STAGE_B + ((r * LDH + kq * 8) << 1),
                       A + (long)(row0 + r) * lda + k0 + kq * 8);
        }
#pragma unroll
        for (int l = 0; l < NB; l++) {
            int i = tid + l * NTH;
            int n = i / KQ, kq = i % KQ;
            cp_async16(bs_u32 + st * B_STAGE_B + ((n * LDH + kq * 8) << 1),
                       Bm + (long)(col0 + n) * ldb + k0 + kq * 8);
        }
    };

    const int kt = K / KBT;
#pragma unroll
    for (int s = 0; s < STAGES - 1; s++) {
        if (s < kt) issue(s, s * KBT);
        asm volatile("cp.async.commit_group;\n");
    }

    for (int t = 0; t < kt; t++) {
        asm volatile("cp.async.wait_group %0;\n" :: "n"(STAGES - 2));
        __syncthreads();
        const int st = t % STAGES;
        const int nx = t + STAGES - 1;
        if (nx < kt) issue(nx % STAGES, nx * KBT);
        asm volatile("cp.async.commit_group;\n");

        const uint32_t aSt = aAddr0 + st * A_STAGE_B;
        const uint32_t bSt = bAddr0 + st * B_STAGE_B;

#pragma unroll
        for (int kc = 0; kc < KBT / 16; kc++) {
            uint32_t af[FM][4], bf[FN][2];
#pragma unroll
            for (int i = 0; i < FM; i++)
                ldsm_x4(af[i], aSt + i * (16 * LDH * 2) + kc * 32);
#pragma unroll
            for (int jp = 0; jp < FN / 2; jp++) {
                uint32_t t4[4];
                ldsm_x4(t4, bSt + jp * (16 * LDH * 2) + kc * 32);
                bf[jp * 2][0] = t4[0];     bf[jp * 2][1] = t4[2];
                bf[jp * 2 + 1][0] = t4[1]; bf[jp * 2 + 1][1] = t4[3];
            }
#pragma unroll
            for (int i = 0; i < FM; i++)
#pragma unroll
                for (int j = 0; j < FN; j++) mma_f16(acc[i][j], af[i], bf[j]);
        }
    }

    __half* Ch = (__half*)Cv + ((EXPC || H16OUT) ? (long)bz * sC : 0);
    float* Cf = (float*)Cv + ((EXPC || H16OUT) ? 0 : (long)bz * sC);
    float facr[FM][2];
    if (FACE) {
        const float* fb = fac + (long)bz * M + row0 + m_base + grp;
#pragma unroll
        for (int i = 0; i < FM; i++) {
            facr[i][0] = 1.f / fb[i * 16];
            facr[i][1] = 1.f / fb[i * 16 + 8];
        }
    }
    float rs[FM][2];
    if (SUMS) {
#pragma unroll
        for (int i = 0; i < FM; i++) { rs[i][0] = 0.f; rs[i][1] = 0.f; }
    }
#pragma unroll
    for (int i = 0; i < FM; i++) {
        int r0 = row0 + m_base + i * 16 + grp;
#pragma unroll
        for (int j = 0; j < FN; j++) {
            int c = col0 + n_base + j * 8 + qid * 2;
            if (EXPC) {
                __half h00 = __float2half_rn(__expf(acc[i][j][0] - EXPSHIFT));
                __half h01 = __float2half_rn(__expf(acc[i][j][1] - EXPSHIFT));
                __half h10 = __float2half_rn(__expf(acc[i][j][2] - EXPSHIFT));
                __half h11 = __float2half_rn(__expf(acc[i][j][3] - EXPSHIFT));
                if (SUMS) {
                    rs[i][0] += __half2float(h00) + __half2float(h01);
                    rs[i][1] += __half2float(h10) + __half2float(h11);
                }
                *(__half2*)(Ch + (long)r0 * ldc + c) = __halves2half2(h00, h01);
                *(__half2*)(Ch + (long)(r0 + 8) * ldc + c) = __halves2half2(h10, h11);
            } else {
                float2 v0 = {acc[i][j][0], acc[i][j][1]};
                float2 v1 = {acc[i][j][2], acc[i][j][3]};
                if (FACE) {
                    v0.x *= facr[i][0]; v0.y *= facr[i][0];
                    v1.x *= facr[i][1]; v1.y *= facr[i][1];
                }
                if (H16OUT) {
                    *(__half2*)(Ch + (long)r0 * ldc + c) = __floats2half2_rn(v0.x, v0.y);
                    *(__half2*)(Ch + (long)(r0 + 8) * ldc + c) = __floats2half2_rn(v1.x, v1.y);
                } else {
                    *(float2*)(Cf + (long)r0 * ldc + c) = v0;
                    *(float2*)(Cf + (long)(r0 + 8) * ldc + c) = v1;
                }
            }
        }
    }
    if (SUMS) {
#pragma unroll
        for (int i = 0; i < FM; i++)
#pragma unroll
            for (int h = 0; h < 2; h++) {
                float s = rs[i][h];
                s += __shfl_xor_sync(0xffffffffu, s, 1);
                s += __shfl_xor_sync(0xffffffffu, s, 2);
                if (qid == 0)
                    atomicAdd(fac + (long)bz * M + row0 + m_base + i * 16 + grp + h * 8, s);
            }
    }
}

// host-side smem mirrors
static inline int gemm_smem_bytes(int BM, int BN, bool transB) {
    const int STAGES = 3, KBT = 32, LDA_S = KBT + 4;
    int a = STAGES * BM * LDA_S;
    int b = transB ? STAGES * BN * LDA_S : STAGES * KBT * (BN + 8);
    return (a + b) * 4;
}
static inline int gemm_f16_smem_bytes(int BM, int BN) {
    const int STAGES = 3, LDH = 72;
    return STAGES * (BM + BN) * LDH * 2;
}

// ---------------- launch ----------------------------------------------------
extern "C" void kernel_launch(void* const* d_in, const int* in_sizes, int n_in,
                              void* d_out, int out_size) {
    const float* inputs = (const float*)d_in[0];
    const float* W_in  = (const float*)d_in[2];
    const float* T_mix = (const float*)d_in[3];
    const float* Wq    = (const float*)d_in[4];
    const float* Wk    = (const float*)d_in[5];
    const float* Wv    = (const float*)d_in[6];
    const float* W_out = (const float*)d_in[7];
    const float* A     = (const float*)d_in[8];

    float* out = (float*)d_out;
    float* mgt = out;
    float* kal = out + (long)B_ * Q_ * N_ * F_;

    float *CP, *WinT, *WqkvT, *fac;
    __half *cat, *qk, *vT, *S, *WcombT16, *Wcat16;
    cudaGetSymbolAddress((void**)&cat, g_cat);
    cudaGetSymbolAddress((void**)&qk, g_qk);
    cudaGetSymbolAddress((void**)&vT, g_vT);
    cudaGetSymbolAddress((void**)&S, g_S);
    cudaGetSymbolAddress((void**)&CP, g_CP);
    cudaGetSymbolAddress((void**)&WinT, g_WinT);
    cudaGetSymbolAddress((void**)&WqkvT, g_WqkvT);
    cudaGetSymbolAddress((void**)&WcombT16, g_WcombT16);
    cudaGetSymbolAddress((void**)&Wcat16, g_Wcat16);
    cudaGetSymbolAddress((void**)&fac, g_fac);

    const long sNN = (long)N_ * N_;
    const long sNF = (long)N_ * F_;
    const long sQK = (long)N_ * 2 * D_;
    const long sVT = (long)D_ * N_;
    const long sCAT = (long)N_ * LDCAT;

    // tf32 instances (weight combos, CP chain, Kalman)
    auto kWC  = gemm_tc<128, 64,  2, 2, false, false, 0,  false, false, false, true,  2>;
    auto kCP  = gemm_tc<128, 128, 2, 4, false, true,  0,  false, true,  true,  false, 2>;
    auto kKAL = gemm_tc<128, 64,  2, 2, false, true,  N_, true,  false, false, false, 2>;
    // fp16 instances
    auto kQKP  = gemm_f16<128, 128, false, false, false, true,  2>;   // qk proj
    auto kVT   = gemm_f16<128, 128, false, false, false, true,  2>;   // vT proj
    auto kQK16 = gemm_f16<128, 128, true,  true,  false, false, 2>;   // K4
    auto kAV16 = gemm_f16<128, 128, false, false, true,  true,  2>;   // K6 -> o
    auto kMGT  = gemm_f16<128, 64,  false, false, false, false, 2>;   // K7 (fp32 out)

    const int smNN64 = gemm_smem_bytes(128, 64, false);
    const int smNN   = gemm_smem_bytes(128, 128, false);
    const int smF16  = gemm_f16_smem_bytes(128, 128);
    const int smF1664 = gemm_f16_smem_bytes(128, 64);
    cudaFuncSetAttribute(kWC,   cudaFuncAttributeMaxDynamicSharedMemorySize, smNN64);
    cudaFuncSetAttribute(kCP,   cudaFuncAttributeMaxDynamicSharedMemorySize, smNN);
    cudaFuncSetAttribute(kKAL,  cudaFuncAttributeMaxDynamicSharedMemorySize, smNN64);
    cudaFuncSetAttribute(kQKP,  cudaFuncAttributeMaxDynamicSharedMemorySize, smF16);
    cudaFuncSetAttribute(kVT,   cudaFuncAttributeMaxDynamicSharedMemorySize, smF16);
    cudaFuncSetAttribute(kQK16, cudaFuncAttributeMaxDynamicSharedMemorySize, smF16);
    cudaFuncSetAttribute(kAV16, cudaFuncAttributeMaxDynamicSharedMemorySize, smF16);
    cudaFuncSetAttribute(kMGT,  cudaFuncAttributeMaxDynamicSharedMemorySize, smF1664);

    // setup + weight combos
    setup_kernel<<<((long)B_ * N_ * F_ + 255) / 256, 256>>>(
        inputs, T_mix, W_in, Wq, Wk, Wv, W_out, A);
    wcat_kernel<<<(F_ * D_ + 255) / 256, 256>>>();
    kWC<<<dim3(1, 3 * D_ / 128, 1), 128, smNN64>>>(
        WqkvT, WinT, WcombT16, nullptr, nullptr,
        3 * D_, F_, D_, D_, F_, F_, 0, 0, 0, 0, 0, 1.f, 0.f);

    // qk = tmp16 @ Wcomb_qk^T  (fp16, K=64 single k-tile)
    kQKP<<<dim3(4, BQN / 128, 1), 256, smF16>>>(
        cat, WcombT16, qk, nullptr,
        BQN, 2 * D_, F_, LDCAT, F_, 2 * D_, 0, 0, 0);

    // K4: S = exp(q@k^T - 8) fp16, rowsums -> fac
    kQK16<<<dim3(4, 4, NBQ), 256, smF16>>>(
        qk, qk + D_, S, fac,
        N_, N_, D_, 2 * D_, 2 * D_, N_, sQK, sQK, sNN);

    // vT[bq] = Wcomb_v @ tmp16[bq]^T  (fp16, K=64)
    kVT<<<dim3(4, 2, NBQ), 256, smF16>>>(
        WcombT16 + (long)2 * D_ * F_, cat, vT, nullptr,
        D_, N_, F_, F_, LDCAT, N_, 0, sCAT, sVT);

    // K6: o = (S @ vT^T) * (1/rowsum), fp16 into cat cols 64..319
    kAV16<<<dim3(2, 4, NBQ), 256, smF16>>>(
        S, vT, cat + F_, fac,
        N_, D_, N_, N_, N_, LDCAT, sNN, sVT, sCAT);

    // K7: mgt = cat @ Wcat^T  (K=320: tmp@Wio^T + o@Wout^T in one GEMM)
    kMGT<<<dim3(1, BQN / 128, 1), 256, smF1664>>>(
        cat, Wcat16, mgt, nullptr,
        BQN, F_, LDCAT, LDCAT, LDCAT, F_, 0, 0, 0);

    // CP chain: c_{k+j} = c_k @ c_j + c_k + c_j
    float* c1 = CP;
    float* c2 = CP + sNN;
    float* c4 = CP + 3 * sNN;
    float* c8 = CP + 7 * sNN;
    kCP<<<dim3(4, 4, 1), 256, smNN>>>(c1, c1, c2, c1, c1,
        N_, N_, N_, N_, N_, N_, N_, 0, 0, 0, 0, 1.f, 1.f);
    kCP<<<dim3(4, 8, 1), 256, smNN>>>(CP, c2, CP + 2 * sNN, CP, c2,
        2 * N_, N_, N_, N_, N_, N_, N_, 0, 0, 0, 0, 1.f, 1.f);
    kCP<<<dim3(4, 16, 1), 256, smNN>>>(CP, c4, CP + 4 * sNN, CP, c4,
        4 * N_, N_, N_, N_, N_, N_, N_, 0, 0, 0, 0, 1.f, 1.f);
    kCP<<<dim3(4, 16, 1), 256, smNN>>>(CP, c8, CP + 8 * sNN, CP, c8,
        4 * N_, N_, N_, N_, N_, N_, N_, 0, 0, 0, 0, 1.f, 1.f);

    // Kalman: kal[b, t] = c_{t+1} @ mu0[b] + mu0[b]
    const float* mu0 = inputs + (long)(P_ - 1) * sNF;
    kKAL<<<dim3(1, 12 * N_ / 128, B_), 128, smNN64>>>(
        CP, mu0, kal, mu0, nullptr,
        12 * N_, F_, N_, N_, F_, F_, F_,
        0, (long)P_ * sNF, (long)Q_ * sNF, (long)P_ * sNF, 1.f, 1.f);
}